// round 14
// baseline (speedup 1.0000x reference)
#include <cuda_runtime.h>
#include <cuda_bf16.h>
#include <cuda_fp16.h>
#include <math.h>
#include <stdint.h>

#define BB    2
#define SS    4096
#define HIDN  2048
#define HVN   32
#define HKN   16
#define CONVD 8192
#define KEYD  2048
#define VALD  4096
#define NCHK  64
#define MROWS (BB*SS)

// ---------------- device scratch ----------------
__device__ float g_mixed[(size_t)BB*SS*CONVD];
__device__ float g_z    [(size_t)BB*SS*VALD];
__device__ float g_qn   [(size_t)BB*HKN*SS*128];
__device__ float g_kn   [(size_t)BB*HKN*SS*128];
__device__ float g_v    [(size_t)BB*HVN*SS*128];
__device__ float g_core [(size_t)BB*HVN*SS*128];
__device__ float g_beta [(size_t)BB*SS*HVN];
__device__ float g_gg   [(size_t)BB*SS*HVN];

__device__ __half g_hs_hi [(size_t)MROWS*HIDN];
__device__ __half g_hs_lo [(size_t)MROWS*HIDN];
__device__ __half g_wqkv_h[(size_t)CONVD*HIDN];  // [N,K]
__device__ __half g_wz_h  [(size_t)VALD*HIDN];
__device__ __half g_wout_h[(size_t)HIDN*VALD];
__device__ __half g_act_hi[(size_t)MROWS*VALD];
__device__ __half g_act_lo[(size_t)MROWS*VALD];

// ---------------- helpers ----------------
__device__ __forceinline__ uint32_t smem_u32(const void* p) {
    uint32_t a;
    asm("{ .reg .u64 t; cvta.to.shared.u64 t, %1; cvt.u32.u64 %0, t; }" : "=r"(a) : "l"(p));
    return a;
}
__device__ __forceinline__ void ldsm4(uint32_t* r, uint32_t addr) {
    asm volatile("ldmatrix.sync.aligned.m8n8.x4.shared.b16 {%0,%1,%2,%3}, [%4];"
        : "=r"(r[0]), "=r"(r[1]), "=r"(r[2]), "=r"(r[3]) : "r"(addr));
}
__device__ __forceinline__ void mma16816f(float* c, const uint32_t* a, const uint32_t* b) {
    asm volatile("mma.sync.aligned.m16n8k16.row.col.f32.f16.f16.f32 "
        "{%0,%1,%2,%3}, {%4,%5,%6,%7}, {%8,%9}, {%0,%1,%2,%3};"
        : "+f"(c[0]), "+f"(c[1]), "+f"(c[2]), "+f"(c[3])
        : "r"(a[0]), "r"(a[1]), "r"(a[2]), "r"(a[3]), "r"(b[0]), "r"(b[1]));
}
__device__ __forceinline__ void mma16816b(float* c, const uint32_t* a, const uint32_t* b) {
    asm volatile("mma.sync.aligned.m16n8k16.row.col.f32.bf16.bf16.f32 "
        "{%0,%1,%2,%3}, {%4,%5,%6,%7}, {%8,%9}, {%0,%1,%2,%3};"
        : "+f"(c[0]), "+f"(c[1]), "+f"(c[2]), "+f"(c[3])
        : "r"(a[0]), "r"(a[1]), "r"(a[2]), "r"(a[3]), "r"(b[0]), "r"(b[1]));
}
__device__ __forceinline__ void cp16(uint32_t dst, const void* src) {
    asm volatile("cp.async.cg.shared.global [%0], [%1], 16;" :: "r"(dst), "l"(src));
}

// ---------------- split kernels (fp16 hi/lo) ----------------
__global__ __launch_bounds__(256) void split_kernel(
    const float* __restrict__ in, __half* __restrict__ hi, __half* __restrict__ lo, size_t n)
{
    size_t i = (size_t)blockIdx.x * 256 + threadIdx.x;
    size_t stride = (size_t)gridDim.x * 256;
    for (; i < n; i += stride) {
        float v = in[i];
        __half h = __float2half_rn(v);
        hi[i] = h;
        lo[i] = __float2half_rn(v - __half2float(h));
    }
}

__global__ __launch_bounds__(256) void tsplit_all_kernel(
    const float* __restrict__ Wq, __half* __restrict__ qh,
    const float* __restrict__ Wz, __half* __restrict__ zh,
    const float* __restrict__ Wo, __half* __restrict__ oh)
{
    __shared__ float tile[32][33];
    int n = blockIdx.x;
    const float* W; __half* Thi; int K, N, bx, by;
    if (n < 16384)      { W = Wq; Thi = qh; K = HIDN; N = CONVD; bx = n & 255; by = n >> 8; }
    else if (n < 24576) { n -= 16384; W = Wz; Thi = zh; K = HIDN; N = VALD; bx = n & 127; by = n >> 7; }
    else                { n -= 24576; W = Wo; Thi = oh; K = VALD; N = HIDN; bx = n & 63;  by = n >> 6; }
    int tx = threadIdx.x & 31, ty = threadIdx.x >> 5;
    for (int i = ty; i < 32; i += 8)
        tile[i][tx] = W[(size_t)(by*32 + i) * N + bx*32 + tx];
    __syncthreads();
    for (int i = ty; i < 32; i += 8)
        Thi[(size_t)(bx*32 + i) * K + by*32 + tx] = __float2half_rn(tile[tx][i]);
}

// ---------------- HMMA fp16x2 GEMM (proven) ----------------
#define GS_ROW   80
#define GS_ARR   (128*GS_ROW)
#define GS_STAGE (3*GS_ARR)
#define GEMM_SMEM (2*GS_STAGE)

__global__ __launch_bounds__(256, 2) void hmma_gemm_kernel(
    const __half* __restrict__ Ahi, const __half* __restrict__ Alo,
    const __half* __restrict__ Bh,
    float* __restrict__ C, int M, int N, int K)
{
    extern __shared__ char smem[];
    uint32_t sb = smem_u32(smem);
    int t = threadIdx.x;
    int m0 = blockIdx.x * 128;
    int n0 = blockIdx.y * 128;
    int w = t >> 5, l = t & 31;
    int wm = w & 3, wn = w >> 2;

    const __half* srcs[3] = { Ahi, Alo, Bh };
    int rowbase[3];
    rowbase[0] = m0; rowbase[1] = m0; rowbase[2] = n0;

    float acc[2][8][4];
#pragma unroll
    for (int i = 0; i < 2; i++)
#pragma unroll
        for (int j = 0; j < 8; j++)
#pragma unroll
            for (int r = 0; r < 4; r++) acc[i][j][r] = 0.f;

    int KT = K >> 5;

    auto load_stage = [&](int s, int k0) {
        uint32_t stb = sb + s * GS_STAGE;
#pragma unroll
        for (int c = 0; c < 6; c++) {
            int idx = t + c * 256;
            int arr = idx >> 9;
            int within = idx & 511;
            int row = within >> 2, ch = within & 3;
            const __half* src = srcs[arr] + (size_t)(rowbase[arr] + row) * K + k0 + ch * 8;
            cp16(stb + arr * GS_ARR + row * GS_ROW + ch * 16, src);
        }
        asm volatile("cp.async.commit_group;");
    };

    load_stage(0, 0);

    int a_off = (wm * 32 + (l & 15)) * GS_ROW + ((l >> 4) * 16);
    int b_off = (wn * 64 + (l & 7) + ((l >> 4) << 3)) * GS_ROW + (((l >> 3) & 1) * 16);

    for (int kt = 0; kt < KT; kt++) {
        if (kt + 1 < KT) load_stage((kt + 1) & 1, (kt + 1) << 5);
        if (kt + 1 < KT) asm volatile("cp.async.wait_group 1;");
        else             asm volatile("cp.async.wait_group 0;");
        __syncthreads();

        uint32_t stb = sb + (kt & 1) * GS_STAGE;
#pragma unroll
        for (int ks = 0; ks < 2; ks++) {
            uint32_t ah[2][4], al[2][4];
#pragma unroll
            for (int mt = 0; mt < 2; mt++) {
                uint32_t aa = stb + a_off + mt * 16 * GS_ROW + ks * 32;
                ldsm4(ah[mt], aa);
                ldsm4(al[mt], aa + GS_ARR);
            }
#pragma unroll
            for (int ntp = 0; ntp < 4; ntp++) {
                uint32_t ba = stb + 2 * GS_ARR + b_off + ntp * 16 * GS_ROW + ks * 32;
                uint32_t bh[4];
                ldsm4(bh, ba);
#pragma unroll
                for (int mt = 0; mt < 2; mt++) {
                    mma16816f(acc[mt][2*ntp],   ah[mt], bh);
                    mma16816f(acc[mt][2*ntp],   al[mt], bh);
                    mma16816f(acc[mt][2*ntp+1], ah[mt], bh + 2);
                    mma16816f(acc[mt][2*ntp+1], al[mt], bh + 2);
                }
            }
        }
        __syncthreads();
    }

#pragma unroll
    for (int mt = 0; mt < 2; mt++) {
        int row = m0 + wm * 32 + mt * 16 + (l >> 2);
        int colb = n0 + wn * 64 + 2 * (l & 3);
#pragma unroll
        for (int nt = 0; nt < 8; nt++) {
            int col = colb + nt * 8;
            float2 v0; v0.x = acc[mt][nt][0]; v0.y = acc[mt][nt][1];
            float2 v1; v1.x = acc[mt][nt][2]; v1.y = acc[mt][nt][3];
            *(float2*)&C[(size_t)row * N + col] = v0;
            *(float2*)&C[(size_t)(row + 8) * N + col] = v1;
        }
    }
}

// ---------------- beta / g projections ----------------
#define BG_RG 4
__global__ __launch_bounds__(256) void bg_kernel(
    const float* __restrict__ hs, const float* __restrict__ W_b, const float* __restrict__ W_a,
    const float* __restrict__ dt_bias, const float* __restrict__ A_log,
    float* __restrict__ beta, float* __restrict__ gg)
{
    __shared__ float hsm[BG_RG * HIDN];
    __shared__ float red[4 * BG_RG * 64];
    int r0 = blockIdx.x * BG_RG;
    int t = threadIdx.x;
    for (int o = t; o < BG_RG * HIDN / 4; o += 256)
        ((float4*)hsm)[o] = ((const float4*)(hs + (size_t)r0 * HIDN))[o];
    __syncthreads();

    int out = t & 63, part = t >> 6;
    const float* Wp = (out < 32) ? (W_b + out) : (W_a + out - 32);
    float acc[BG_RG];
#pragma unroll
    for (int r = 0; r < BG_RG; r++) acc[r] = 0.f;
    int kbase = part * (HIDN / 4);
    for (int kk = 0; kk < HIDN / 4; kk++) {
        int k = kbase + kk;
        float w2 = Wp[(size_t)k * 32];
#pragma unroll
        for (int r = 0; r < BG_RG; r++) acc[r] += hsm[r * HIDN + k] * w2;
    }
#pragma unroll
    for (int r = 0; r < BG_RG; r++) red[(part * BG_RG + r) * 64 + out] = acc[r];
    __syncthreads();

    int rr = t >> 6, oo = t & 63;
    float s = red[(0*BG_RG+rr)*64+oo] + red[(1*BG_RG+rr)*64+oo]
            + red[(2*BG_RG+rr)*64+oo] + red[(3*BG_RG+rr)*64+oo];
    size_t row = (size_t)r0 + rr;
    if (oo < 32) {
        beta[row * 32 + oo] = 1.f / (1.f + expf(-s));
    } else {
        int h = oo - 32;
        float x = s + dt_bias[h];
        float sp = (x > 20.f) ? x : log1pf(expf(x));
        gg[row * 32 + h] = -expf(A_log[h]) * sp;
    }
}

// ---------------- conv1d(K=4 causal) + SiLU + split + l2norm(q,k) ----------------
__global__ __launch_bounds__(128) void conv_silu_kernel(
    const float* __restrict__ mixed, const float* __restrict__ conv_w,
    float* __restrict__ qn, float* __restrict__ kn, float* __restrict__ vout)
{
    int unit = blockIdx.x;
    int s0 = blockIdx.y * 8;
    int b = blockIdx.z;
    int d = threadIdx.x;
    int base = (unit < 16) ? unit * 128
             : (unit < 32) ? KEYD + (unit - 16) * 128
             : 2 * KEYD + (unit - 32) * 128;
    int c = base + d;
    const float* mb = mixed + (size_t)b * SS * CONVD + c;

    float m[11];
#pragma unroll
    for (int j = 0; j < 11; j++) {
        int sp = s0 + j - 3;
        m[j] = (sp >= 0) ? mb[(size_t)sp * CONVD] : 0.f;
    }
    float w0 = conv_w[(size_t)c*4+0], w1 = conv_w[(size_t)c*4+1],
          w2 = conv_w[(size_t)c*4+2], w3 = conv_w[(size_t)c*4+3];
    float xs[8];
#pragma unroll
    for (int sp = 0; sp < 8; sp++) {
        float a = w0*m[sp] + w1*m[sp+1] + w2*m[sp+2] + w3*m[sp+3];
        xs[sp] = a / (1.f + expf(-a));
    }

    if (unit < 32) {
        __shared__ float red[8][4];
#pragma unroll
        for (int sp = 0; sp < 8; sp++) {
            float ss = xs[sp]*xs[sp];
#pragma unroll
            for (int off = 16; off > 0; off >>= 1) ss += __shfl_down_sync(0xffffffffu, ss, off);
            if ((d & 31) == 0) red[sp][d >> 5] = ss;
        }
        __syncthreads();
        float* dst; float extra;
        if (unit < 16) { dst = qn + (((size_t)(b*HKN+unit))*SS)*128; extra = 0.08838834764831845f; }
        else           { dst = kn + (((size_t)(b*HKN+unit-16))*SS)*128; extra = 1.f; }
#pragma unroll
        for (int sp = 0; sp < 8; sp++) {
            float tot = red[sp][0]+red[sp][1]+red[sp][2]+red[sp][3];
            float scale = rsqrtf(tot + 1e-6f) * extra;
            dst[(size_t)(s0+sp)*128 + d] = xs[sp] * scale;
        }
    } else {
        float* dst = vout + (((size_t)(b*HVN+unit-32))*SS)*128;
#pragma unroll
        for (int sp = 0; sp < 8; sp++)
            dst[(size_t)(s0+sp)*128 + d] = xs[sp];
    }
}

// ---------------- chunked gated delta rule: W/A/X'/O1 on tensor cores, shared fragments ----------------
#define DBF_OFF   116224
#define DBF_ARR   17408
#define DBF_PITCH 272
#define DOF_K     0
#define DOF_Q     34816
#define DOF_ST    69632
#define DELTA_SMEM_BYTES (116224 + 6*17408)   // 220672

__global__ __launch_bounds__(256, 1) void delta_kernel(
    const float* __restrict__ qn, const float* __restrict__ kn,
    const float* __restrict__ vv, const float* __restrict__ beta,
    const float* __restrict__ gg, float* __restrict__ core)
{
    extern __shared__ float sm[];
    char* smc = (char*)sm;
    uint32_t sbase = smem_u32(sm);
    float* st  = sm;          // [64 v][128 d]
    float* KT  = st + 8192;   // [128 d][65]
    float* Vs  = KT + 8320;   // [64 i][64 v]
    float* Wm  = Vs + 4096;   // [64][64]
    float* Am  = Wm + 4096;   // [64][64]
    float* gcs = Am + 4096;
    float* bet = gcs + 64;
    float* egs = bet + 64;
    float* edl = egs + 64;

    int t = threadIdx.x;
    int wrp = t >> 5, l = t & 31;
    int vs = blockIdx.x & 1;
    int h  = (blockIdx.x >> 1) & 31;
    int b  = blockIdx.x >> 6;
    int vo = vs * 64;
    int hk = h >> 1;
    const float* qb = qn + (size_t)(b*HKN+hk)*SS*128;
    const float* kb = kn + (size_t)(b*HKN+hk)*SS*128;
    const float* vb = vv + (size_t)(b*HVN+h)*SS*128;
    const float* bp = beta + (size_t)b*SS*HVN + h;
    const float* gp = gg   + (size_t)b*SS*HVN + h;
    float* cb = core + (size_t)(b*HVN+h)*SS*128;

    for (int i = t; i < 8192; i += 256) st[i] = 0.f;
    __syncthreads();

    for (int ck = 0; ck < NCHK; ck++) {
        size_t srow = (size_t)ck * 64;
        const float* qr = qb + srow*128;
        const float* kr = kb + srow*128;
        const float* vr = vb + srow*128;
        for (int idx = t; idx < 8192; idx += 256) {
            int i = idx >> 7, d = idx & 127;
            int ro = i*DBF_PITCH + d*2;
            float kvv = kr[idx];
            float qvv = qr[idx];
            KT[d*65 + i] = kvv;
            __nv_bfloat16 kh = __float2bfloat16_rn(kvv);
            __nv_bfloat16 qh = __float2bfloat16_rn(qvv);
            *(__nv_bfloat16*)(smc + DBF_OFF + DOF_K + ro) = kh;
            *(__nv_bfloat16*)(smc + DBF_OFF + DOF_K + DBF_ARR + ro) = __float2bfloat16_rn(kvv - __bfloat162float(kh));
            *(__nv_bfloat16*)(smc + DBF_OFF + DOF_Q + ro) = qh;
            *(__nv_bfloat16*)(smc + DBF_OFF + DOF_Q + DBF_ARR + ro) = __float2bfloat16_rn(qvv - __bfloat162float(qh));
            float sv = st[idx];
            __nv_bfloat16 sh = __float2bfloat16_rn(sv);
            *(__nv_bfloat16*)(smc + DBF_OFF + DOF_ST + ro) = sh;
            *(__nv_bfloat16*)(smc + DBF_OFF + DOF_ST + DBF_ARR + ro) = __float2bfloat16_rn(sv - __bfloat162float(sh));
        }
        for (int idx = t; idx < 4096; idx += 256) {
            int i = idx >> 6, c = idx & 63;
            Vs[idx] = vr[i*128 + vo + c];
        }
        if (t < 64) {
            bet[t] = bp[(srow + t)*HVN];
            edl[t] = gp[(srow + t)*HVN];
        }
        __syncthreads();
        if (t == 0) {
            float r = 0.f;
            for (int i = 0; i < 64; i++) { r += edl[i]; gcs[i] = r; }
        }
        __syncthreads();
        if (t < 64) {
            egs[t] = expf(gcs[t]);
            edl[t] = expf(gcs[63] - gcs[t]);
        }
        __syncthreads();

        // ---- 4 products together, shared fragments. warp w -> sub-tile (r0, c0g) of all 4.
        // products: W=K.K^T  A=Q.K^T  X'=K.S^T  O1=Q.S^T   (bf16x3 each)
        {
            uint32_t a_row = (l & 15);
            uint32_t a_col = (l >> 4) * 16;
            uint32_t b_row = (l & 7) + ((l >> 4) << 3);
            uint32_t b_col = ((l >> 3) & 1) * 16;
            int r0 = (wrp >> 1) << 4, c0g = (wrp & 1) << 5;

            float aW[4][4], aA[4][4], aX[4][4], aO[4][4];
#pragma unroll
            for (int i = 0; i < 4; i++)
#pragma unroll
                for (int j = 0; j < 4; j++) { aW[i][j]=0.f; aA[i][j]=0.f; aX[i][j]=0.f; aO[i][j]=0.f; }

            uint32_t kab = sbase + DBF_OFF + DOF_K + (r0 + a_row)*DBF_PITCH + a_col;
            uint32_t qab = sbase + DBF_OFF + DOF_Q + (r0 + a_row)*DBF_PITCH + a_col;
            uint32_t kbb = sbase + DBF_OFF + DOF_K + (c0g + b_row)*DBF_PITCH + b_col;
            uint32_t sbb = sbase + DBF_OFF + DOF_ST + (c0g + b_row)*DBF_PITCH + b_col;
#pragma unroll
            for (int kt = 0; kt < 8; kt++) {
                uint32_t kh_a[4], kl_a[4], qh_a[4], ql_a[4];
                ldsm4(kh_a, kab + kt*32);
                ldsm4(kl_a, kab + kt*32 + DBF_ARR);
                ldsm4(qh_a, qab + kt*32);
                ldsm4(ql_a, qab + kt*32 + DBF_ARR);
#pragma unroll
                for (int nn = 0; nn < 2; nn++) {
                    uint32_t bkh[4], bkl[4], bsh[4], bsl[4];
                    ldsm4(bkh, kbb + nn*16*DBF_PITCH + kt*32);
                    ldsm4(bkl, kbb + nn*16*DBF_PITCH + kt*32 + DBF_ARR);
                    ldsm4(bsh, sbb + nn*16*DBF_PITCH + kt*32);
                    ldsm4(bsl, sbb + nn*16*DBF_PITCH + kt*32 + DBF_ARR);
#pragma unroll
                    for (int half = 0; half < 2; half++) {
                        int n8 = 2*nn + half;
                        mma16816b(aW[n8], kh_a, bkh + 2*half);
                        mma16816b(aW[n8], kh_a, bkl + 2*half);
                        mma16816b(aW[n8], kl_a, bkh + 2*half);
                        mma16816b(aA[n8], qh_a, bkh + 2*half);
                        mma16816b(aA[n8], qh_a, bkl + 2*half);
                        mma16816b(aA[n8], ql_a, bkh + 2*half);
                        mma16816b(aX[n8], kh_a, bsh + 2*half);
                        mma16816b(aX[n8], kh_a, bsl + 2*half);
                        mma16816b(aX[n8], kl_a, bsh + 2*half);
                        mma16816b(aO[n8], qh_a, bsh + 2*half);
                        mma16816b(aO[n8], qh_a, bsl + 2*half);
                        mma16816b(aO[n8], ql_a, bsh + 2*half);
                    }
                }
            }
            // epilogues
#pragma unroll
            for (int n8 = 0; n8 < 4; n8++) {
#pragma unroll
                for (int e = 0; e < 4; e++) {
                    int row = r0 + (l >> 2) + ((e >> 1) ? 8 : 0);
                    int col = c0g + n8*8 + 2*(l & 3) + (e & 1);
                    // W (strict lower)
                    float wv = 0.f;
                    if (col < row) wv = bet[row] * expf(gcs[row] - gcs[col]) * aW[n8][e];
                    Wm[row*64 + col] = wv;
                    // A (lower incl diag)
                    float av = 0.f;
                    if (col <= row) av = expf(gcs[row] - gcs[col]) * aA[n8][e];
                    Am[row*64 + col] = av;
                    // X' : Vs = beta*(V - e^{gc}*dot)
                    Vs[row*64 + col] = bet[row] * (Vs[row*64 + col] - egs[row] * aX[n8][e]);
                    // O1 -> cb
                    cb[(srow + row)*128 + vo + col] = egs[row] * aO[n8][e];
                }
            }
        }
        __syncthreads();
        // ---- forward substitution: v_new = (I+W)^{-1} X ----
        if (t < 64) {
            float x[64];
#pragma unroll
            for (int i = 0; i < 64; i++) {
                float a0 = Vs[i*64 + t], a1 = 0.f;
                int j = 0;
#pragma unroll
                for (; j + 2 <= i; j += 2) {
                    a0 -= Wm[i*64 + j]   * x[j];
                    a1 -= Wm[i*64 + j+1] * x[j+1];
                }
                if (j < i) a0 -= Wm[i*64 + j] * x[j];
                x[i] = a0 + a1;
            }
#pragma unroll
            for (int i = 0; i < 64; i++) Vs[i*64 + t] = x[i];
        }
        __syncthreads();
        // ---- out: cb += Am @ v_new ----
        {
            int r0 = (t >> 3) * 2, c0 = (t & 7) * 8;
            float o2[2][8];
#pragma unroll
            for (int i = 0; i < 2; i++)
#pragma unroll
                for (int j = 0; j < 8; j++) o2[i][j] = 0.f;
            for (int jj = 0; jj < 64; jj++) {
                float a0 = Am[r0*64 + jj], a1 = Am[(r0+1)*64 + jj];
                float4 v0 = *(float4*)&Vs[jj*64 + c0];
                float4 v1 = *(float4*)&Vs[jj*64 + c0 + 4];
                float vw[8] = {v0.x,v0.y,v0.z,v0.w,v1.x,v1.y,v1.z,v1.w};
#pragma unroll
                for (int j = 0; j < 8; j++) {
                    o2[0][j] += a0*vw[j];
                    o2[1][j] += a1*vw[j];
                }
            }
#pragma unroll
            for (int i = 0; i < 2; i++) {
                int r = r0 + i;
#pragma unroll
                for (int j = 0; j < 8; j += 4) {
                    float4 v = *(float4*)&cb[(srow + r)*128 + vo + c0 + j];
                    v.x += o2[i][j];
                    v.y += o2[i][j+1];
                    v.z += o2[i][j+2];
                    v.w += o2[i][j+3];
                    *(float4*)&cb[(srow + r)*128 + vo + c0 + j] = v;
                }
            }
        }
        // ---- state update: st[v][d] = st*e^{gl} + sum_i vn[i][v]*edl[i]*k[i][d] ----
        {
            int d0 = (t >> 4) * 8, v0 = (t & 15) * 4;
            float acc[4][8];
#pragma unroll
            for (int i = 0; i < 4; i++)
#pragma unroll
                for (int j = 0; j < 8; j++) acc[i][j] = 0.f;
            for (int i = 0; i < 64; i++) {
                float el = edl[i];
                float vn[4];
#pragma unroll
                for (int x2 = 0; x2 < 4; x2++) vn[x2] = Vs[i*64 + v0 + x2] * el;
                float kd[8];
#pragma unroll
                for (int j = 0; j < 8; j++) kd[j] = KT[(d0+j)*65 + i];
#pragma unroll
                for (int x2 = 0; x2 < 4; x2++)
#pragma unroll
                    for (int j = 0; j < 8; j++) acc[x2][j] += vn[x2]*kd[j];
            }
            float egl = expf(gcs[63]);
#pragma unroll
            for (int x2 = 0; x2 < 4; x2++)
#pragma unroll
                for (int j = 0; j < 8; j += 4) {
                    float4 s = *(float4*)&st[(v0+x2)*128 + d0 + j];
                    s.x = s.x*egl + acc[x2][j];
                    s.y = s.y*egl + acc[x2][j+1];
                    s.z = s.z*egl + acc[x2][j+2];
                    s.w = s.w*egl + acc[x2][j+3];
                    *(float4*)&st[(v0+x2)*128 + d0 + j] = s;
                }
        }
        __syncthreads();
    }
}

// ---------------- gated RMSNorm + SiLU(z) gate -> fp16 hi/lo (2 s-positions/block) ----------------
__global__ __launch_bounds__(256) void normgate_kernel(
    const float* __restrict__ core, const float* __restrict__ z,
    const float* __restrict__ norm_weight,
    __half* __restrict__ act_hi, __half* __restrict__ act_lo)
{
    int g = threadIdx.x >> 7;           // 0,1: sub-block
    int s = blockIdx.x * 2 + g;
    int h = blockIdx.y, b = blockIdx.z;
    int d = threadIdx.x & 127;
    __shared__ float red[2][4];
    size_t ci = ((size_t)(b*HVN + h)*SS + s)*128 + d;
    float v = core[ci];
    float ss = v*v;
#pragma unroll
    for (int off = 16; off > 0; off >>= 1) ss += __shfl_down_sync(0xffffffffu, ss, off);
    if ((d & 31) == 0) red[g][(d >> 5) & 3] = ss;
    __syncthreads();
    float var = (red[g][0]+red[g][1]+red[g][2]+red[g][3]) * (1.f/128.f);
    float scale = rsqrtf(var + 1e-6f) * norm_weight[d];
    size_t zi = ((size_t)b*SS + s)*VALD + h*128 + d;
    float zv = z[zi];
    float gate = zv / (1.f + expf(-zv));
    float val = v * scale * gate;
    __half hv = __float2half_rn(val);
    act_hi[zi] = hv;
    act_lo[zi] = __float2half_rn(val - __half2float(hv));
}

extern "C" void kernel_launch(void* const* d_in, const int* in_sizes, int n_in,
                              void* d_out, int out_size) {
    const float* hs     = (const float*)d_in[0];
    const float* W_qkv  = (const float*)d_in[1];
    const float* conv_w = (const float*)d_in[2];
    const float* W_z    = (const float*)d_in[3];
    const float* W_b    = (const float*)d_in[4];
    const float* W_a    = (const float*)d_in[5];
    const float* dt_b   = (const float*)d_in[6];
    const float* A_log  = (const float*)d_in[7];
    const float* normw  = (const float*)d_in[8];
    const float* W_out  = (const float*)d_in[9];
    float* out = (float*)d_out;

    float *mixed, *z, *qn, *kn, *v, *core, *beta, *gg;
    cudaGetSymbolAddress((void**)&mixed, g_mixed);
    cudaGetSymbolAddress((void**)&z,     g_z);
    cudaGetSymbolAddress((void**)&qn,    g_qn);
    cudaGetSymbolAddress((void**)&kn,    g_kn);
    cudaGetSymbolAddress((void**)&v,     g_v);
    cudaGetSymbolAddress((void**)&core,  g_core);
    cudaGetSymbolAddress((void**)&beta,  g_beta);
    cudaGetSymbolAddress((void**)&gg,    g_gg);

    __half *hs_hi, *hs_lo, *wqkv_h, *wz_h, *wout_h, *act_hi, *act_lo;
    cudaGetSymbolAddress((void**)&hs_hi,  g_hs_hi);
    cudaGetSymbolAddress((void**)&hs_lo,  g_hs_lo);
    cudaGetSymbolAddress((void**)&wqkv_h, g_wqkv_h);
    cudaGetSymbolAddress((void**)&wz_h,   g_wz_h);
    cudaGetSymbolAddress((void**)&wout_h, g_wout_h);
    cudaGetSymbolAddress((void**)&act_hi, g_act_hi);
    cudaGetSymbolAddress((void**)&act_lo, g_act_lo);

    cudaFuncSetAttribute(delta_kernel, cudaFuncAttributeMaxDynamicSharedMemorySize, DELTA_SMEM_BYTES);
    cudaFuncSetAttribute(hmma_gemm_kernel, cudaFuncAttributeMaxDynamicSharedMemorySize, GEMM_SMEM);

    static cudaStream_t s2 = nullptr;
    static cudaEvent_t e_fork = nullptr, e_g2 = nullptr;
    if (s2 == nullptr) {
        cudaStreamCreateWithFlags(&s2, cudaStreamNonBlocking);
        cudaEventCreateWithFlags(&e_fork, cudaEventDisableTiming);
        cudaEventCreateWithFlags(&e_g2, cudaEventDisableTiming);
    }

    // 0) weight transposes, hs split
    tsplit_all_kernel<<<32768, 256>>>(W_qkv, wqkv_h, W_z, wz_h, W_out, wout_h);
    split_kernel<<<2048, 256>>>(hs, hs_hi, hs_lo, (size_t)MROWS*HIDN);

    // fork: gemm2 depends only on splits
    cudaEventRecord(e_fork, 0);
    cudaStreamWaitEvent(s2, e_fork, 0);
    hmma_gemm_kernel<<<dim3(MROWS/128, VALD/128), 256, GEMM_SMEM, s2>>>(
        hs_hi, hs_lo, wz_h, z, MROWS, VALD, HIDN);
    cudaEventRecord(e_g2, s2);

    // 1) mixed = hs @ W_qkv
    hmma_gemm_kernel<<<dim3(MROWS/128, CONVD/128), 256, GEMM_SMEM>>>(
        hs_hi, hs_lo, wqkv_h, mixed, MROWS, CONVD, HIDN);

    // main chain
    bg_kernel<<<MROWS/BG_RG, 256>>>(hs, W_b, W_a, dt_b, A_log, beta, gg);
    conv_silu_kernel<<<dim3(64, SS/8, BB), 128>>>(mixed, conv_w, qn, kn, v);
    delta_kernel<<<BB*HVN*2, 256, DELTA_SMEM_BYTES>>>(qn, kn, v, beta, gg, core);

    // join: normgate needs z
    cudaStreamWaitEvent(0, e_g2, 0);
    normgate_kernel<<<dim3(SS/2, HVN, BB), 256>>>(core, z, normw, act_hi, act_lo);

    // out = act @ W_out
    hmma_gemm_kernel<<<dim3(MROWS/128, HIDN/128), 256, GEMM_SMEM>>>(
        act_hi, act_lo, wout_h, out, MROWS, HIDN, VALD);
}

// round 15
// speedup vs baseline: 1.0257x; 1.0257x over previous
#include <cuda_runtime.h>
#include <cuda_bf16.h>
#include <cuda_fp16.h>
#include <math.h>
#include <stdint.h>

#define BB    2
#define SS    4096
#define HIDN  2048
#define HVN   32
#define HKN   16
#define CONVD 8192
#define KEYD  2048
#define VALD  4096
#define NCHK  64
#define MROWS (BB*SS)

// ---------------- device scratch ----------------
__device__ float g_mixed[(size_t)BB*SS*CONVD];
__device__ float g_z    [(size_t)BB*SS*VALD];
__device__ float g_qn   [(size_t)BB*HKN*SS*128];
__device__ float g_kn   [(size_t)BB*HKN*SS*128];
__device__ float g_v    [(size_t)BB*HVN*SS*128];
__device__ float g_core [(size_t)BB*HVN*SS*128];
__device__ float g_beta [(size_t)BB*SS*HVN];
__device__ float g_gg   [(size_t)BB*SS*HVN];

__device__ __half g_hs_hi [(size_t)MROWS*HIDN];
__device__ __half g_hs_lo [(size_t)MROWS*HIDN];
__device__ __half g_wqkv_h[(size_t)CONVD*HIDN];  // [N,K]
__device__ __half g_wz_h  [(size_t)VALD*HIDN];
__device__ __half g_wout_h[(size_t)HIDN*VALD];
__device__ __half g_act_hi[(size_t)MROWS*VALD];
__device__ __half g_act_lo[(size_t)MROWS*VALD];

// ---------------- helpers ----------------
__device__ __forceinline__ uint32_t smem_u32(const void* p) {
    uint32_t a;
    asm("{ .reg .u64 t; cvta.to.shared.u64 t, %1; cvt.u32.u64 %0, t; }" : "=r"(a) : "l"(p));
    return a;
}
__device__ __forceinline__ void ldsm4(uint32_t* r, uint32_t addr) {
    asm volatile("ldmatrix.sync.aligned.m8n8.x4.shared.b16 {%0,%1,%2,%3}, [%4];"
        : "=r"(r[0]), "=r"(r[1]), "=r"(r[2]), "=r"(r[3]) : "r"(addr));
}
__device__ __forceinline__ void mma16816f(float* c, const uint32_t* a, const uint32_t* b) {
    asm volatile("mma.sync.aligned.m16n8k16.row.col.f32.f16.f16.f32 "
        "{%0,%1,%2,%3}, {%4,%5,%6,%7}, {%8,%9}, {%0,%1,%2,%3};"
        : "+f"(c[0]), "+f"(c[1]), "+f"(c[2]), "+f"(c[3])
        : "r"(a[0]), "r"(a[1]), "r"(a[2]), "r"(a[3]), "r"(b[0]), "r"(b[1]));
}
__device__ __forceinline__ void mma16816b(float* c, const uint32_t* a, const uint32_t* b) {
    asm volatile("mma.sync.aligned.m16n8k16.row.col.f32.bf16.bf16.f32 "
        "{%0,%1,%2,%3}, {%4,%5,%6,%7}, {%8,%9}, {%0,%1,%2,%3};"
        : "+f"(c[0]), "+f"(c[1]), "+f"(c[2]), "+f"(c[3])
        : "r"(a[0]), "r"(a[1]), "r"(a[2]), "r"(a[3]), "r"(b[0]), "r"(b[1]));
}
__device__ __forceinline__ void cp16(uint32_t dst, const void* src) {
    asm volatile("cp.async.cg.shared.global [%0], [%1], 16;" :: "r"(dst), "l"(src));
}
__device__ __forceinline__ uint32_t pack_bf2(float a, float b) {
    __nv_bfloat162 h;
    h.x = __float2bfloat16_rn(a);
    h.y = __float2bfloat16_rn(b);
    return *(uint32_t*)&h;
}
__device__ __forceinline__ uint32_t pack_bf2_res(float a, float b, uint32_t hi) {
    __nv_bfloat162 h = *(__nv_bfloat162*)&hi;
    __nv_bfloat162 r;
    r.x = __float2bfloat16_rn(a - __bfloat162float(h.x));
    r.y = __float2bfloat16_rn(b - __bfloat162float(h.y));
    return *(uint32_t*)&r;
}

// ---------------- split kernels (fp16 hi/lo) ----------------
__global__ __launch_bounds__(256) void split_kernel(
    const float* __restrict__ in, __half* __restrict__ hi, __half* __restrict__ lo, size_t n)
{
    size_t i = (size_t)blockIdx.x * 256 + threadIdx.x;
    size_t stride = (size_t)gridDim.x * 256;
    for (; i < n; i += stride) {
        float v = in[i];
        __half h = __float2half_rn(v);
        hi[i] = h;
        lo[i] = __float2half_rn(v - __half2float(h));
    }
}

__global__ __launch_bounds__(256) void tsplit_all_kernel(
    const float* __restrict__ Wq, __half* __restrict__ qh,
    const float* __restrict__ Wz, __half* __restrict__ zh,
    const float* __restrict__ Wo, __half* __restrict__ oh)
{
    __shared__ float tile[32][33];
    int n = blockIdx.x;
    const float* W; __half* Thi; int K, N, bx, by;
    if (n < 16384)      { W = Wq; Thi = qh; K = HIDN; N = CONVD; bx = n & 255; by = n >> 8; }
    else if (n < 24576) { n -= 16384; W = Wz; Thi = zh; K = HIDN; N = VALD; bx = n & 127; by = n >> 7; }
    else                { n -= 24576; W = Wo; Thi = oh; K = VALD; N = HIDN; bx = n & 63;  by = n >> 6; }
    int tx = threadIdx.x & 31, ty = threadIdx.x >> 5;
    for (int i = ty; i < 32; i += 8)
        tile[i][tx] = W[(size_t)(by*32 + i) * N + bx*32 + tx];
    __syncthreads();
    for (int i = ty; i < 32; i += 8)
        Thi[(size_t)(bx*32 + i) * K + by*32 + tx] = __float2half_rn(tile[tx][i]);
}

// ---------------- HMMA fp16x2 GEMM (proven) ----------------
#define GS_ROW   80
#define GS_ARR   (128*GS_ROW)
#define GS_STAGE (3*GS_ARR)
#define GEMM_SMEM (2*GS_STAGE)

__global__ __launch_bounds__(256, 2) void hmma_gemm_kernel(
    const __half* __restrict__ Ahi, const __half* __restrict__ Alo,
    const __half* __restrict__ Bh,
    float* __restrict__ C, int M, int N, int K)
{
    extern __shared__ char smem[];
    uint32_t sb = smem_u32(smem);
    int t = threadIdx.x;
    int m0 = blockIdx.x * 128;
    int n0 = blockIdx.y * 128;
    int w = t >> 5, l = t & 31;
    int wm = w & 3, wn = w >> 2;

    const __half* srcs[3] = { Ahi, Alo, Bh };
    int rowbase[3];
    rowbase[0] = m0; rowbase[1] = m0; rowbase[2] = n0;

    float acc[2][8][4];
#pragma unroll
    for (int i = 0; i < 2; i++)
#pragma unroll
        for (int j = 0; j < 8; j++)
#pragma unroll
            for (int r = 0; r < 4; r++) acc[i][j][r] = 0.f;

    int KT = K >> 5;

    auto load_stage = [&](int s, int k0) {
        uint32_t stb = sb + s * GS_STAGE;
#pragma unroll
        for (int c = 0; c < 6; c++) {
            int idx = t + c * 256;
            int arr = idx >> 9;
            int within = idx & 511;
            int row = within >> 2, ch = within & 3;
            const __half* src = srcs[arr] + (size_t)(rowbase[arr] + row) * K + k0 + ch * 8;
            cp16(stb + arr * GS_ARR + row * GS_ROW + ch * 16, src);
        }
        asm volatile("cp.async.commit_group;");
    };

    load_stage(0, 0);

    int a_off = (wm * 32 + (l & 15)) * GS_ROW + ((l >> 4) * 16);
    int b_off = (wn * 64 + (l & 7) + ((l >> 4) << 3)) * GS_ROW + (((l >> 3) & 1) * 16);

    for (int kt = 0; kt < KT; kt++) {
        if (kt + 1 < KT) load_stage((kt + 1) & 1, (kt + 1) << 5);
        if (kt + 1 < KT) asm volatile("cp.async.wait_group 1;");
        else             asm volatile("cp.async.wait_group 0;");
        __syncthreads();

        uint32_t stb = sb + (kt & 1) * GS_STAGE;
#pragma unroll
        for (int ks = 0; ks < 2; ks++) {
            uint32_t ah[2][4], al[2][4];
#pragma unroll
            for (int mt = 0; mt < 2; mt++) {
                uint32_t aa = stb + a_off + mt * 16 * GS_ROW + ks * 32;
                ldsm4(ah[mt], aa);
                ldsm4(al[mt], aa + GS_ARR);
            }
#pragma unroll
            for (int ntp = 0; ntp < 4; ntp++) {
                uint32_t ba = stb + 2 * GS_ARR + b_off + ntp * 16 * GS_ROW + ks * 32;
                uint32_t bh[4];
                ldsm4(bh, ba);
#pragma unroll
                for (int mt = 0; mt < 2; mt++) {
                    mma16816f(acc[mt][2*ntp],   ah[mt], bh);
                    mma16816f(acc[mt][2*ntp],   al[mt], bh);
                    mma16816f(acc[mt][2*ntp+1], ah[mt], bh + 2);
                    mma16816f(acc[mt][2*ntp+1], al[mt], bh + 2);
                }
            }
        }
        __syncthreads();
    }

#pragma unroll
    for (int mt = 0; mt < 2; mt++) {
        int row = m0 + wm * 32 + mt * 16 + (l >> 2);
        int colb = n0 + wn * 64 + 2 * (l & 3);
#pragma unroll
        for (int nt = 0; nt < 8; nt++) {
            int col = colb + nt * 8;
            float2 v0; v0.x = acc[mt][nt][0]; v0.y = acc[mt][nt][1];
            float2 v1; v1.x = acc[mt][nt][2]; v1.y = acc[mt][nt][3];
            *(float2*)&C[(size_t)row * N + col] = v0;
            *(float2*)&C[(size_t)(row + 8) * N + col] = v1;
        }
    }
}

// ---------------- beta / g projections ----------------
#define BG_RG 4
__global__ __launch_bounds__(256) void bg_kernel(
    const float* __restrict__ hs, const float* __restrict__ W_b, const float* __restrict__ W_a,
    const float* __restrict__ dt_bias, const float* __restrict__ A_log,
    float* __restrict__ beta, float* __restrict__ gg)
{
    __shared__ float hsm[BG_RG * HIDN];
    __shared__ float red[4 * BG_RG * 64];
    int r0 = blockIdx.x * BG_RG;
    int t = threadIdx.x;
    for (int o = t; o < BG_RG * HIDN / 4; o += 256)
        ((float4*)hsm)[o] = ((const float4*)(hs + (size_t)r0 * HIDN))[o];
    __syncthreads();

    int out = t & 63, part = t >> 6;
    const float* Wp = (out < 32) ? (W_b + out) : (W_a + out - 32);
    float acc[BG_RG];
#pragma unroll
    for (int r = 0; r < BG_RG; r++) acc[r] = 0.f;
    int kbase = part * (HIDN / 4);
    for (int kk = 0; kk < HIDN / 4; kk++) {
        int k = kbase + kk;
        float w2 = Wp[(size_t)k * 32];
#pragma unroll
        for (int r = 0; r < BG_RG; r++) acc[r] += hsm[r * HIDN + k] * w2;
    }
#pragma unroll
    for (int r = 0; r < BG_RG; r++) red[(part * BG_RG + r) * 64 + out] = acc[r];
    __syncthreads();

    int rr = t >> 6, oo = t & 63;
    float s = red[(0*BG_RG+rr)*64+oo] + red[(1*BG_RG+rr)*64+oo]
            + red[(2*BG_RG+rr)*64+oo] + red[(3*BG_RG+rr)*64+oo];
    size_t row = (size_t)r0 + rr;
    if (oo < 32) {
        beta[row * 32 + oo] = 1.f / (1.f + expf(-s));
    } else {
        int h = oo - 32;
        float x = s + dt_bias[h];
        float sp = (x > 20.f) ? x : log1pf(expf(x));
        gg[row * 32 + h] = -expf(A_log[h]) * sp;
    }
}

// ---------------- conv1d(K=4 causal) + SiLU + split + l2norm(q,k) ----------------
__global__ __launch_bounds__(128) void conv_silu_kernel(
    const float* __restrict__ mixed, const float* __restrict__ conv_w,
    float* __restrict__ qn, float* __restrict__ kn, float* __restrict__ vout)
{
    int unit = blockIdx.x;
    int s0 = blockIdx.y * 8;
    int b = blockIdx.z;
    int d = threadIdx.x;
    int base = (unit < 16) ? unit * 128
             : (unit < 32) ? KEYD + (unit - 16) * 128
             : 2 * KEYD + (unit - 32) * 128;
    int c = base + d;
    const float* mb = mixed + (size_t)b * SS * CONVD + c;

    float m[11];
#pragma unroll
    for (int j = 0; j < 11; j++) {
        int sp = s0 + j - 3;
        m[j] = (sp >= 0) ? mb[(size_t)sp * CONVD] : 0.f;
    }
    float w0 = conv_w[(size_t)c*4+0], w1 = conv_w[(size_t)c*4+1],
          w2 = conv_w[(size_t)c*4+2], w3 = conv_w[(size_t)c*4+3];
    float xs[8];
#pragma unroll
    for (int sp = 0; sp < 8; sp++) {
        float a = w0*m[sp] + w1*m[sp+1] + w2*m[sp+2] + w3*m[sp+3];
        xs[sp] = a / (1.f + expf(-a));
    }

    if (unit < 32) {
        __shared__ float red[8][4];
#pragma unroll
        for (int sp = 0; sp < 8; sp++) {
            float ss = xs[sp]*xs[sp];
#pragma unroll
            for (int off = 16; off > 0; off >>= 1) ss += __shfl_down_sync(0xffffffffu, ss, off);
            if ((d & 31) == 0) red[sp][d >> 5] = ss;
        }
        __syncthreads();
        float* dst; float extra;
        if (unit < 16) { dst = qn + (((size_t)(b*HKN+unit))*SS)*128; extra = 0.08838834764831845f; }
        else           { dst = kn + (((size_t)(b*HKN+unit-16))*SS)*128; extra = 1.f; }
#pragma unroll
        for (int sp = 0; sp < 8; sp++) {
            float tot = red[sp][0]+red[sp][1]+red[sp][2]+red[sp][3];
            float scale = rsqrtf(tot + 1e-6f) * extra;
            dst[(size_t)(s0+sp)*128 + d] = xs[sp] * scale;
        }
    } else {
        float* dst = vout + (((size_t)(b*HVN+unit-32))*SS)*128;
#pragma unroll
        for (int sp = 0; sp < 8; sp++)
            dst[(size_t)(s0+sp)*128 + d] = xs[sp];
    }
}

// ---------------- chunked gated delta rule: W/A/X'/O1 on tensor cores ----------------
#define DBF_OFF   116224
#define DBF_ARR   17408
#define DBF_PITCH 272
#define DOF_K     0
#define DOF_Q     34816
#define DOF_ST    69632
#define DELTA_SMEM_BYTES (116224 + 6*17408)   // 220672

__global__ __launch_bounds__(256, 1) void delta_kernel(
    const float* __restrict__ qn, const float* __restrict__ kn,
    const float* __restrict__ vv, const float* __restrict__ beta,
    const float* __restrict__ gg, float* __restrict__ core)
{
    extern __shared__ float sm[];
    char* smc = (char*)sm;
    uint32_t sbase = smem_u32(sm);
    float* st  = sm;          // [64 v][128 d]
    float* KT  = st + 8192;   // [128 d][65]
    float* Vs  = KT + 8320;   // [64 i][64 v]
    float* Wm  = Vs + 4096;   // [64][64]
    float* Am  = Wm + 4096;   // [64][64]
    float* gcs = Am + 4096;
    float* bet = gcs + 64;
    float* egs = bet + 64;
    float* edl = egs + 64;

    int t = threadIdx.x;
    int wrp = t >> 5, l = t & 31;
    int vs = blockIdx.x & 1;
    int h  = (blockIdx.x >> 1) & 31;
    int b  = blockIdx.x >> 6;
    int vo = vs * 64;
    int hk = h >> 1;
    const float* qb = qn + (size_t)(b*HKN+hk)*SS*128;
    const float* kb = kn + (size_t)(b*HKN+hk)*SS*128;
    const float* vb = vv + (size_t)(b*HVN+h)*SS*128;
    const float* bp = beta + (size_t)b*SS*HVN + h;
    const float* gp = gg   + (size_t)b*SS*HVN + h;
    float* cb = core + (size_t)(b*HVN+h)*SS*128;

    for (int i = t; i < 8192; i += 256) st[i] = 0.f;
    __syncthreads();

    for (int ck = 0; ck < NCHK; ck++) {
        size_t srow = (size_t)ck * 64;
        const float* qr = qb + srow*128;
        const float* kr = kb + srow*128;
        const float* vr = vb + srow*128;
        // vectorized staging: float4 per thread-iter
        for (int idx = t; idx < 2048; idx += 256) {
            int i = idx >> 5, d = (idx & 31) * 4;
            float4 kv = *(const float4*)&kr[i*128 + d];
            float4 qv = *(const float4*)&qr[i*128 + d];
            float4 sv = *(const float4*)&st[i*128 + d];
            KT[(d+0)*65 + i] = kv.x; KT[(d+1)*65 + i] = kv.y;
            KT[(d+2)*65 + i] = kv.z; KT[(d+3)*65 + i] = kv.w;
            int ro = i*DBF_PITCH + d*2;
            uint32_t kh0 = pack_bf2(kv.x, kv.y), kh1 = pack_bf2(kv.z, kv.w);
            uint32_t qh0 = pack_bf2(qv.x, qv.y), qh1 = pack_bf2(qv.z, qv.w);
            uint32_t sh0 = pack_bf2(sv.x, sv.y), sh1 = pack_bf2(sv.z, sv.w);
            *(uint32_t*)(smc + DBF_OFF + DOF_K + ro)     = kh0;
            *(uint32_t*)(smc + DBF_OFF + DOF_K + ro + 4) = kh1;
            *(uint32_t*)(smc + DBF_OFF + DOF_K + DBF_ARR + ro)     = pack_bf2_res(kv.x, kv.y, kh0);
            *(uint32_t*)(smc + DBF_OFF + DOF_K + DBF_ARR + ro + 4) = pack_bf2_res(kv.z, kv.w, kh1);
            *(uint32_t*)(smc + DBF_OFF + DOF_Q + ro)     = qh0;
            *(uint32_t*)(smc + DBF_OFF + DOF_Q + ro + 4) = qh1;
            *(uint32_t*)(smc + DBF_OFF + DOF_Q + DBF_ARR + ro)     = pack_bf2_res(qv.x, qv.y, qh0);
            *(uint32_t*)(smc + DBF_OFF + DOF_Q + DBF_ARR + ro + 4) = pack_bf2_res(qv.z, qv.w, qh1);
            *(uint32_t*)(smc + DBF_OFF + DOF_ST + ro)     = sh0;
            *(uint32_t*)(smc + DBF_OFF + DOF_ST + ro + 4) = sh1;
            *(uint32_t*)(smc + DBF_OFF + DOF_ST + DBF_ARR + ro)     = pack_bf2_res(sv.x, sv.y, sh0);
            *(uint32_t*)(smc + DBF_OFF + DOF_ST + DBF_ARR + ro + 4) = pack_bf2_res(sv.z, sv.w, sh1);
        }
        for (int idx = t; idx < 1024; idx += 256) {
            int i = idx >> 4, c = (idx & 15) * 4;
            *(float4*)&Vs[i*64 + c] = *(const float4*)&vr[i*128 + vo + c];
        }
        if (t < 64) {
            bet[t] = bp[(srow + t)*HVN];
            edl[t] = gp[(srow + t)*HVN];   // raw g
        }
        __syncthreads();
        // warp-scan prefix sum over 64 gate values (warp 0; lane i handles pair 2i,2i+1)
        if (t < 32) {
            float a = edl[2*t], b2 = edl[2*t+1];
            float run = a + b2;
#pragma unroll
            for (int o = 1; o < 32; o <<= 1) {
                float n = __shfl_up_sync(0xffffffffu, run, o);
                if (t >= o) run += n;
            }
            gcs[2*t+1] = run;
            gcs[2*t]   = run - b2;
        }
        __syncthreads();
        if (t < 64) {
            egs[t] = expf(gcs[t]);
            edl[t] = expf(gcs[63] - gcs[t]);
        }
        __syncthreads();

        // ---- 4 products (bf16x3): 0:W=K.K^T  1:A=Q.K^T  2:X'=K.S^T  3:O1=Q.S^T
        {
            uint32_t a_row = (l & 15);
            uint32_t a_col = (l >> 4) * 16;
            uint32_t b_row = (l & 7) + ((l >> 4) << 3);
            uint32_t b_col = ((l >> 3) & 1) * 16;
#pragma unroll
            for (int tt = 0; tt < 4; tt++) {
                int tile = wrp + tt*8;
                int prod = tile >> 3;
                int sub = tile & 7;
                int r0 = (sub >> 1) << 4, c0g = (sub & 1) << 5;
                uint32_t abase = sbase + DBF_OFF + ((prod & 1) ? DOF_Q : DOF_K);
                uint32_t bbase = sbase + DBF_OFF + ((prod >> 1) ? DOF_ST : DOF_K);
                float acc[4][4];
#pragma unroll
                for (int a2 = 0; a2 < 4; a2++)
#pragma unroll
                    for (int a3 = 0; a3 < 4; a3++) acc[a2][a3] = 0.f;
#pragma unroll
                for (int kt = 0; kt < 8; kt++) {
                    uint32_t aaddr = abase + (r0 + a_row)*DBF_PITCH + kt*32 + a_col;
                    uint32_t ah[4], al[4];
                    ldsm4(ah, aaddr);
                    ldsm4(al, aaddr + DBF_ARR);
#pragma unroll
                    for (int nn = 0; nn < 2; nn++) {
                        uint32_t baddr = bbase + (c0g + nn*16 + b_row)*DBF_PITCH + kt*32 + b_col;
                        uint32_t bh[4], bl[4];
                        ldsm4(bh, baddr);
                        ldsm4(bl, baddr + DBF_ARR);
                        mma16816b(acc[2*nn],   ah, bh);
                        mma16816b(acc[2*nn],   ah, bl);
                        mma16816b(acc[2*nn],   al, bh);
                        mma16816b(acc[2*nn+1], ah, bh + 2);
                        mma16816b(acc[2*nn+1], ah, bl + 2);
                        mma16816b(acc[2*nn+1], al, bh + 2);
                    }
                }
#pragma unroll
                for (int n8 = 0; n8 < 4; n8++) {
#pragma unroll
                    for (int e = 0; e < 4; e++) {
                        int row = r0 + (l >> 2) + ((e >> 1) ? 8 : 0);
                        int col = c0g + n8*8 + 2*(l & 3) + (e & 1);
                        float dot = acc[n8][e];
                        if (prod == 0) {
                            float outv = 0.f;
                            if (col < row) outv = bet[row] * expf(gcs[row] - gcs[col]) * dot;
                            Wm[row*64 + col] = outv;
                        } else if (prod == 1) {
                            float outv = 0.f;
                            if (col <= row) outv = expf(gcs[row] - gcs[col]) * dot;
                            Am[row*64 + col] = outv;
                        } else if (prod == 2) {
                            Vs[row*64 + col] = bet[row] * (Vs[row*64 + col] - egs[row] * dot);
                        } else {
                            cb[(srow + row)*128 + vo + col] = egs[row] * dot;
                        }
                    }
                }
            }
        }
        __syncthreads();
        // ---- forward substitution ----
        if (t < 64) {
            float x[64];
#pragma unroll
            for (int i = 0; i < 64; i++) {
                float a0 = Vs[i*64 + t], a1 = 0.f;
                int j = 0;
#pragma unroll
                for (; j + 2 <= i; j += 2) {
                    a0 -= Wm[i*64 + j]   * x[j];
                    a1 -= Wm[i*64 + j+1] * x[j+1];
                }
                if (j < i) a0 -= Wm[i*64 + j] * x[j];
                x[i] = a0 + a1;
            }
#pragma unroll
            for (int i = 0; i < 64; i++) Vs[i*64 + t] = x[i];
        }
        __syncthreads();
        // ---- out: cb += Am @ v_new ----
        {
            int r0 = (t >> 3) * 2, c0 = (t & 7) * 8;
            float o2[2][8];
#pragma unroll
            for (int i = 0; i < 2; i++)
#pragma unroll
                for (int j = 0; j < 8; j++) o2[i][j] = 0.f;
            for (int jj = 0; jj < 64; jj++) {
                float a0 = Am[r0*64 + jj], a1 = Am[(r0+1)*64 + jj];
                float4 v0 = *(float4*)&Vs[jj*64 + c0];
                float4 v1 = *(float4*)&Vs[jj*64 + c0 + 4];
                float vw[8] = {v0.x,v0.y,v0.z,v0.w,v1.x,v1.y,v1.z,v1.w};
#pragma unroll
                for (int j = 0; j < 8; j++) {
                    o2[0][j] += a0*vw[j];
                    o2[1][j] += a1*vw[j];
                }
            }
#pragma unroll
            for (int i = 0; i < 2; i++) {
                int r = r0 + i;
#pragma unroll
                for (int j = 0; j < 8; j += 4) {
                    float4 v = *(float4*)&cb[(srow + r)*128 + vo + c0 + j];
                    v.x += o2[i][j];
                    v.y += o2[i][j+1];
                    v.z += o2[i][j+2];
                    v.w += o2[i][j+3];
                    *(float4*)&cb[(srow + r)*128 + vo + c0 + j] = v;
                }
            }
        }
        // ---- state update: st[v][d] = st*e^{gl} + sum_i vn[i][v]*edl[i]*k[i][d] ----
        {
            int d0 = (t >> 4) * 8, v0 = (t & 15) * 4;
            float acc[4][8];
#pragma unroll
            for (int i = 0; i < 4; i++)
#pragma unroll
                for (int j = 0; j < 8; j++) acc[i][j] = 0.f;
            for (int i = 0; i < 64; i++) {
                float el = edl[i];
                float vn[4];
#pragma unroll
                for (int x2 = 0; x2 < 4; x2++) vn[x2] = Vs[i*64 + v0 + x2] * el;
                float kd[8];
#pragma unroll
                for (int j = 0; j < 8; j++) kd[j] = KT[(d0+j)*65 + i];
#pragma unroll
                for (int x2 = 0; x2 < 4; x2++)
#pragma unroll
                    for (int j = 0; j < 8; j++) acc[x2][j] += vn[x2]*kd[j];
            }
            float egl = expf(gcs[63]);
#pragma unroll
            for (int x2 = 0; x2 < 4; x2++)
#pragma unroll
                for (int j = 0; j < 8; j += 4) {
                    float4 s = *(float4*)&st[(v0+x2)*128 + d0 + j];
                    s.x = s.x*egl + acc[x2][j];
                    s.y = s.y*egl + acc[x2][j+1];
                    s.z = s.z*egl + acc[x2][j+2];
                    s.w = s.w*egl + acc[x2][j+3];
                    *(float4*)&st[(v0+x2)*128 + d0 + j] = s;
                }
        }
        __syncthreads();
    }
}

// ---------------- gated RMSNorm + SiLU(z) gate -> fp16 hi/lo ----------------
__global__ __launch_bounds__(128) void normgate_kernel(
    const float* __restrict__ core, const float* __restrict__ z,
    const float* __restrict__ norm_weight,
    __half* __restrict__ act_hi, __half* __restrict__ act_lo)
{
    int s = blockIdx.x, h = blockIdx.y, b = blockIdx.z;
    int d = threadIdx.x;
    __shared__ float red[4];
    size_t ci = ((size_t)(b*HVN + h)*SS + s)*128 + d;
    float v = core[ci];
    float ss = v*v;
#pragma unroll
    for (int off = 16; off > 0; off >>= 1) ss += __shfl_down_sync(0xffffffffu, ss, off);
    if ((d & 31) == 0) red[d >> 5] = ss;
    __syncthreads();
    float var = (red[0]+red[1]+red[2]+red[3]) * (1.f/128.f);
    float scale = rsqrtf(var + 1e-6f) * norm_weight[d];
    size_t zi = ((size_t)b*SS + s)*VALD + h*128 + d;
    float zv = z[zi];
    float gate = zv / (1.f + expf(-zv));
    float val = v * scale * gate;
    __half hv = __float2half_rn(val);
    act_hi[zi] = hv;
    act_lo[zi] = __float2half_rn(val - __half2float(hv));
}

extern "C" void kernel_launch(void* const* d_in, const int* in_sizes, int n_in,
                              void* d_out, int out_size) {
    const float* hs     = (const float*)d_in[0];
    const float* W_qkv  = (const float*)d_in[1];
    const float* conv_w = (const float*)d_in[2];
    const float* W_z    = (const float*)d_in[3];
    const float* W_b    = (const float*)d_in[4];
    const float* W_a    = (const float*)d_in[5];
    const float* dt_b   = (const float*)d_in[6];
    const float* A_log  = (const float*)d_in[7];
    const float* normw  = (const float*)d_in[8];
    const float* W_out  = (const float*)d_in[9];
    float* out = (float*)d_out;

    float *mixed, *z, *qn, *kn, *v, *core, *beta, *gg;
    cudaGetSymbolAddress((void**)&mixed, g_mixed);
    cudaGetSymbolAddress((void**)&z,     g_z);
    cudaGetSymbolAddress((void**)&qn,    g_qn);
    cudaGetSymbolAddress((void**)&kn,    g_kn);
    cudaGetSymbolAddress((void**)&v,     g_v);
    cudaGetSymbolAddress((void**)&core,  g_core);
    cudaGetSymbolAddress((void**)&beta,  g_beta);
    cudaGetSymbolAddress((void**)&gg,    g_gg);

    __half *hs_hi, *hs_lo, *wqkv_h, *wz_h, *wout_h, *act_hi, *act_lo;
    cudaGetSymbolAddress((void**)&hs_hi,  g_hs_hi);
    cudaGetSymbolAddress((void**)&hs_lo,  g_hs_lo);
    cudaGetSymbolAddress((void**)&wqkv_h, g_wqkv_h);
    cudaGetSymbolAddress((void**)&wz_h,   g_wz_h);
    cudaGetSymbolAddress((void**)&wout_h, g_wout_h);
    cudaGetSymbolAddress((void**)&act_hi, g_act_hi);
    cudaGetSymbolAddress((void**)&act_lo, g_act_lo);

    cudaFuncSetAttribute(delta_kernel, cudaFuncAttributeMaxDynamicSharedMemorySize, DELTA_SMEM_BYTES);
    cudaFuncSetAttribute(hmma_gemm_kernel, cudaFuncAttributeMaxDynamicSharedMemorySize, GEMM_SMEM);

    static cudaStream_t s2 = nullptr;
    static cudaEvent_t e0 = nullptr, e1 = nullptr, e_bg = nullptr, e_g2 = nullptr;
    if (s2 == nullptr) {
        cudaStreamCreateWithFlags(&s2, cudaStreamNonBlocking);
        cudaEventCreateWithFlags(&e0, cudaEventDisableTiming);
        cudaEventCreateWithFlags(&e1, cudaEventDisableTiming);
        cudaEventCreateWithFlags(&e_bg, cudaEventDisableTiming);
        cudaEventCreateWithFlags(&e_g2, cudaEventDisableTiming);
    }

    // fork immediately: bg needs only hs
    cudaEventRecord(e0, 0);
    cudaStreamWaitEvent(s2, e0, 0);
    bg_kernel<<<MROWS/BG_RG, 256, 0, s2>>>(hs, W_b, W_a, dt_b, A_log, beta, gg);
    cudaEventRecord(e_bg, s2);

    // origin: weight transposes + hs split
    tsplit_all_kernel<<<32768, 256>>>(W_qkv, wqkv_h, W_z, wz_h, W_out, wout_h);
    split_kernel<<<2048, 256>>>(hs, hs_hi, hs_lo, (size_t)MROWS*HIDN);
    cudaEventRecord(e1, 0);

    // s2: gemm2 after splits
    cudaStreamWaitEvent(s2, e1, 0);
    hmma_gemm_kernel<<<dim3(MROWS/128, VALD/128), 256, GEMM_SMEM, s2>>>(
        hs_hi, hs_lo, wz_h, z, MROWS, VALD, HIDN);
    cudaEventRecord(e_g2, s2);

    // origin main chain
    hmma_gemm_kernel<<<dim3(MROWS/128, CONVD/128), 256, GEMM_SMEM>>>(
        hs_hi, hs_lo, wqkv_h, mixed, MROWS, CONVD, HIDN);
    conv_silu_kernel<<<dim3(64, SS/8, BB), 128>>>(mixed, conv_w, qn, kn, v);
    cudaStreamWaitEvent(0, e_bg, 0);
    delta_kernel<<<BB*HVN*2, 256, DELTA_SMEM_BYTES>>>(qn, kn, v, beta, gg, core);

    // join: normgate needs z
    cudaStreamWaitEvent(0, e_g2, 0);
    normgate_kernel<<<dim3(SS, HVN, BB), 128>>>(core, z, normw, act_hi, act_lo);

    // out = act @ W_out
    hmma_gemm_kernel<<<dim3(MROWS/128, HIDN/128), 256, GEMM_SMEM>>>(
        act_hi, act_lo, wout_h, out, MROWS, HIDN, VALD);
}

// round 16
// speedup vs baseline: 1.0779x; 1.0509x over previous
#include <cuda_runtime.h>
#include <cuda_bf16.h>
#include <cuda_fp16.h>
#include <math.h>
#include <stdint.h>

#define BB    2
#define SS    4096
#define HIDN  2048
#define HVN   32
#define HKN   16
#define CONVD 8192
#define KEYD  2048
#define VALD  4096
#define NCHK  64
#define MROWS (BB*SS)

// ---------------- device scratch ----------------
__device__ float g_mixed[(size_t)BB*SS*CONVD];
__device__ float g_z    [(size_t)BB*SS*VALD];
__device__ float g_qn   [(size_t)BB*HKN*SS*128];
__device__ float g_kn   [(size_t)BB*HKN*SS*128];
__device__ float g_v    [(size_t)BB*HVN*SS*128];
__device__ float g_core [(size_t)BB*HVN*SS*128];
__device__ float g_beta [(size_t)BB*SS*HVN];
__device__ float g_gg   [(size_t)BB*SS*HVN];

__device__ __half g_hs_hi [(size_t)MROWS*HIDN];
__device__ __half g_hs_lo [(size_t)MROWS*HIDN];
__device__ __half g_wqkv_h[(size_t)CONVD*HIDN];  // [N,K]
__device__ __half g_wz_h  [(size_t)VALD*HIDN];
__device__ __half g_wout_h[(size_t)HIDN*VALD];
__device__ __half g_act_hi[(size_t)MROWS*VALD];
__device__ __half g_act_lo[(size_t)MROWS*VALD];

// ---------------- helpers ----------------
__device__ __forceinline__ uint32_t smem_u32(const void* p) {
    uint32_t a;
    asm("{ .reg .u64 t; cvta.to.shared.u64 t, %1; cvt.u32.u64 %0, t; }" : "=r"(a) : "l"(p));
    return a;
}
__device__ __forceinline__ void ldsm4(uint32_t* r, uint32_t addr) {
    asm volatile("ldmatrix.sync.aligned.m8n8.x4.shared.b16 {%0,%1,%2,%3}, [%4];"
        : "=r"(r[0]), "=r"(r[1]), "=r"(r[2]), "=r"(r[3]) : "r"(addr));
}
__device__ __forceinline__ void mma16816f(float* c, const uint32_t* a, const uint32_t* b) {
    asm volatile("mma.sync.aligned.m16n8k16.row.col.f32.f16.f16.f32 "
        "{%0,%1,%2,%3}, {%4,%5,%6,%7}, {%8,%9}, {%0,%1,%2,%3};"
        : "+f"(c[0]), "+f"(c[1]), "+f"(c[2]), "+f"(c[3])
        : "r"(a[0]), "r"(a[1]), "r"(a[2]), "r"(a[3]), "r"(b[0]), "r"(b[1]));
}
__device__ __forceinline__ void mma16816b(float* c, const uint32_t* a, const uint32_t* b) {
    asm volatile("mma.sync.aligned.m16n8k16.row.col.f32.bf16.bf16.f32 "
        "{%0,%1,%2,%3}, {%4,%5,%6,%7}, {%8,%9}, {%0,%1,%2,%3};"
        : "+f"(c[0]), "+f"(c[1]), "+f"(c[2]), "+f"(c[3])
        : "r"(a[0]), "r"(a[1]), "r"(a[2]), "r"(a[3]), "r"(b[0]), "r"(b[1]));
}
__device__ __forceinline__ void cp16(uint32_t dst, const void* src) {
    asm volatile("cp.async.cg.shared.global [%0], [%1], 16;" :: "r"(dst), "l"(src));
}
__device__ __forceinline__ uint32_t pack_bf2(float a, float b) {
    __nv_bfloat162 h;
    h.x = __float2bfloat16_rn(a);
    h.y = __float2bfloat16_rn(b);
    return *(uint32_t*)&h;
}
__device__ __forceinline__ uint32_t pack_bf2_res(float a, float b, uint32_t hi) {
    __nv_bfloat162 h = *(__nv_bfloat162*)&hi;
    __nv_bfloat162 r;
    r.x = __float2bfloat16_rn(a - __bfloat162float(h.x));
    r.y = __float2bfloat16_rn(b - __bfloat162float(h.y));
    return *(uint32_t*)&r;
}

// ---------------- split kernels (fp16 hi/lo) ----------------
__global__ __launch_bounds__(256) void split_kernel(
    const float* __restrict__ in, __half* __restrict__ hi, __half* __restrict__ lo, size_t n)
{
    size_t i = (size_t)blockIdx.x * 256 + threadIdx.x;
    size_t stride = (size_t)gridDim.x * 256;
    for (; i < n; i += stride) {
        float v = in[i];
        __half h = __float2half_rn(v);
        hi[i] = h;
        lo[i] = __float2half_rn(v - __half2float(h));
    }
}

__global__ __launch_bounds__(256) void tsplit_all_kernel(
    const float* __restrict__ Wq, __half* __restrict__ qh,
    const float* __restrict__ Wz, __half* __restrict__ zh,
    const float* __restrict__ Wo, __half* __restrict__ oh)
{
    __shared__ float tile[32][33];
    int n = blockIdx.x;
    const float* W; __half* Thi; int K, N, bx, by;
    if (n < 16384)      { W = Wq; Thi = qh; K = HIDN; N = CONVD; bx = n & 255; by = n >> 8; }
    else if (n < 24576) { n -= 16384; W = Wz; Thi = zh; K = HIDN; N = VALD; bx = n & 127; by = n >> 7; }
    else                { n -= 24576; W = Wo; Thi = oh; K = VALD; N = HIDN; bx = n & 63;  by = n >> 6; }
    int tx = threadIdx.x & 31, ty = threadIdx.x >> 5;
    for (int i = ty; i < 32; i += 8)
        tile[i][tx] = W[(size_t)(by*32 + i) * N + bx*32 + tx];
    __syncthreads();
    for (int i = ty; i < 32; i += 8)
        Thi[(size_t)(bx*32 + i) * K + by*32 + tx] = __float2half_rn(tile[tx][i]);
}

// ---------------- HMMA fp16x2 GEMM (proven) ----------------
#define GS_ROW   80
#define GS_ARR   (128*GS_ROW)
#define GS_STAGE (3*GS_ARR)
#define GEMM_SMEM (2*GS_STAGE)

__global__ __launch_bounds__(256, 2) void hmma_gemm_kernel(
    const __half* __restrict__ Ahi, const __half* __restrict__ Alo,
    const __half* __restrict__ Bh,
    float* __restrict__ C, int M, int N, int K)
{
    extern __shared__ char smem[];
    uint32_t sb = smem_u32(smem);
    int t = threadIdx.x;
    int m0 = blockIdx.x * 128;
    int n0 = blockIdx.y * 128;
    int w = t >> 5, l = t & 31;
    int wm = w & 3, wn = w >> 2;

    const __half* srcs[3] = { Ahi, Alo, Bh };
    int rowbase[3];
    rowbase[0] = m0; rowbase[1] = m0; rowbase[2] = n0;

    float acc[2][8][4];
#pragma unroll
    for (int i = 0; i < 2; i++)
#pragma unroll
        for (int j = 0; j < 8; j++)
#pragma unroll
            for (int r = 0; r < 4; r++) acc[i][j][r] = 0.f;

    int KT = K >> 5;

    auto load_stage = [&](int s, int k0) {
        uint32_t stb = sb + s * GS_STAGE;
#pragma unroll
        for (int c = 0; c < 6; c++) {
            int idx = t + c * 256;
            int arr = idx >> 9;
            int within = idx & 511;
            int row = within >> 2, ch = within & 3;
            const __half* src = srcs[arr] + (size_t)(rowbase[arr] + row) * K + k0 + ch * 8;
            cp16(stb + arr * GS_ARR + row * GS_ROW + ch * 16, src);
        }
        asm volatile("cp.async.commit_group;");
    };

    load_stage(0, 0);

    int a_off = (wm * 32 + (l & 15)) * GS_ROW + ((l >> 4) * 16);
    int b_off = (wn * 64 + (l & 7) + ((l >> 4) << 3)) * GS_ROW + (((l >> 3) & 1) * 16);

    for (int kt = 0; kt < KT; kt++) {
        if (kt + 1 < KT) load_stage((kt + 1) & 1, (kt + 1) << 5);
        if (kt + 1 < KT) asm volatile("cp.async.wait_group 1;");
        else             asm volatile("cp.async.wait_group 0;");
        __syncthreads();

        uint32_t stb = sb + (kt & 1) * GS_STAGE;
#pragma unroll
        for (int ks = 0; ks < 2; ks++) {
            uint32_t ah[2][4], al[2][4];
#pragma unroll
            for (int mt = 0; mt < 2; mt++) {
                uint32_t aa = stb + a_off + mt * 16 * GS_ROW + ks * 32;
                ldsm4(ah[mt], aa);
                ldsm4(al[mt], aa + GS_ARR);
            }
#pragma unroll
            for (int ntp = 0; ntp < 4; ntp++) {
                uint32_t ba = stb + 2 * GS_ARR + b_off + ntp * 16 * GS_ROW + ks * 32;
                uint32_t bh[4];
                ldsm4(bh, ba);
#pragma unroll
                for (int mt = 0; mt < 2; mt++) {
                    mma16816f(acc[mt][2*ntp],   ah[mt], bh);
                    mma16816f(acc[mt][2*ntp],   al[mt], bh);
                    mma16816f(acc[mt][2*ntp+1], ah[mt], bh + 2);
                    mma16816f(acc[mt][2*ntp+1], al[mt], bh + 2);
                }
            }
        }
        __syncthreads();
    }

#pragma unroll
    for (int mt = 0; mt < 2; mt++) {
        int row = m0 + wm * 32 + mt * 16 + (l >> 2);
        int colb = n0 + wn * 64 + 2 * (l & 3);
#pragma unroll
        for (int nt = 0; nt < 8; nt++) {
            int col = colb + nt * 8;
            float2 v0; v0.x = acc[mt][nt][0]; v0.y = acc[mt][nt][1];
            float2 v1; v1.x = acc[mt][nt][2]; v1.y = acc[mt][nt][3];
            *(float2*)&C[(size_t)row * N + col] = v0;
            *(float2*)&C[(size_t)(row + 8) * N + col] = v1;
        }
    }
}

// ---------------- beta / g projections ----------------
#define BG_RG 4
__global__ __launch_bounds__(256) void bg_kernel(
    const float* __restrict__ hs, const float* __restrict__ W_b, const float* __restrict__ W_a,
    const float* __restrict__ dt_bias, const float* __restrict__ A_log,
    float* __restrict__ beta, float* __restrict__ gg)
{
    __shared__ float hsm[BG_RG * HIDN];
    __shared__ float red[4 * BG_RG * 64];
    int r0 = blockIdx.x * BG_RG;
    int t = threadIdx.x;
    for (int o = t; o < BG_RG * HIDN / 4; o += 256)
        ((float4*)hsm)[o] = ((const float4*)(hs + (size_t)r0 * HIDN))[o];
    __syncthreads();

    int out = t & 63, part = t >> 6;
    const float* Wp = (out < 32) ? (W_b + out) : (W_a + out - 32);
    float acc[BG_RG];
#pragma unroll
    for (int r = 0; r < BG_RG; r++) acc[r] = 0.f;
    int kbase = part * (HIDN / 4);
    for (int kk = 0; kk < HIDN / 4; kk++) {
        int k = kbase + kk;
        float w2 = Wp[(size_t)k * 32];
#pragma unroll
        for (int r = 0; r < BG_RG; r++) acc[r] += hsm[r * HIDN + k] * w2;
    }
#pragma unroll
    for (int r = 0; r < BG_RG; r++) red[(part * BG_RG + r) * 64 + out] = acc[r];
    __syncthreads();

    int rr = t >> 6, oo = t & 63;
    float s = red[(0*BG_RG+rr)*64+oo] + red[(1*BG_RG+rr)*64+oo]
            + red[(2*BG_RG+rr)*64+oo] + red[(3*BG_RG+rr)*64+oo];
    size_t row = (size_t)r0 + rr;
    if (oo < 32) {
        beta[row * 32 + oo] = 1.f / (1.f + expf(-s));
    } else {
        int h = oo - 32;
        float x = s + dt_bias[h];
        float sp = (x > 20.f) ? x : log1pf(expf(x));
        gg[row * 32 + h] = -expf(A_log[h]) * sp;
    }
}

// ---------------- conv1d(K=4 causal) + SiLU + split + l2norm(q,k) ----------------
__global__ __launch_bounds__(128) void conv_silu_kernel(
    const float* __restrict__ mixed, const float* __restrict__ conv_w,
    float* __restrict__ qn, float* __restrict__ kn, float* __restrict__ vout)
{
    int unit = blockIdx.x;
    int s0 = blockIdx.y * 8;
    int b = blockIdx.z;
    int d = threadIdx.x;
    int base = (unit < 16) ? unit * 128
             : (unit < 32) ? KEYD + (unit - 16) * 128
             : 2 * KEYD + (unit - 32) * 128;
    int c = base + d;
    const float* mb = mixed + (size_t)b * SS * CONVD + c;

    float m[11];
#pragma unroll
    for (int j = 0; j < 11; j++) {
        int sp = s0 + j - 3;
        m[j] = (sp >= 0) ? mb[(size_t)sp * CONVD] : 0.f;
    }
    float w0 = conv_w[(size_t)c*4+0], w1 = conv_w[(size_t)c*4+1],
          w2 = conv_w[(size_t)c*4+2], w3 = conv_w[(size_t)c*4+3];
    float xs[8];
#pragma unroll
    for (int sp = 0; sp < 8; sp++) {
        float a = w0*m[sp] + w1*m[sp+1] + w2*m[sp+2] + w3*m[sp+3];
        xs[sp] = a / (1.f + expf(-a));
    }

    if (unit < 32) {
        __shared__ float red[8][4];
#pragma unroll
        for (int sp = 0; sp < 8; sp++) {
            float ss = xs[sp]*xs[sp];
#pragma unroll
            for (int off = 16; off > 0; off >>= 1) ss += __shfl_down_sync(0xffffffffu, ss, off);
            if ((d & 31) == 0) red[sp][d >> 5] = ss;
        }
        __syncthreads();
        float* dst; float extra;
        if (unit < 16) { dst = qn + (((size_t)(b*HKN+unit))*SS)*128; extra = 0.08838834764831845f; }
        else           { dst = kn + (((size_t)(b*HKN+unit-16))*SS)*128; extra = 1.f; }
#pragma unroll
        for (int sp = 0; sp < 8; sp++) {
            float tot = red[sp][0]+red[sp][1]+red[sp][2]+red[sp][3];
            float scale = rsqrtf(tot + 1e-6f) * extra;
            dst[(size_t)(s0+sp)*128 + d] = xs[sp] * scale;
        }
    } else {
        float* dst = vout + (((size_t)(b*HVN+unit-32))*SS)*128;
#pragma unroll
        for (int sp = 0; sp < 8; sp++)
            dst[(size_t)(s0+sp)*128 + d] = xs[sp];
    }
}

// ---------------- chunked gated delta rule: W/A/X'/O1 + state update on tensor cores ----------------
// fp32 (floats): st[64v][128d] 8192 | Vs 4096 | Wm 4096 | Am 4096 | scalars 256 = 20736 -> 82944 B
// bf16 staging at DBF_OFF: K hi/lo, Q hi/lo, ST hi/lo (each 64r x 272B)
// late staging (overlaps Q+ST region after product phase): KdT[128d][64i] hi/lo pitch 144, VnT[64v][64i] hi/lo pitch 144
#define DBF_OFF   82944
#define DBF_ARR   17408
#define DBF_PITCH 272
#define DOF_K     0
#define DOF_Q     34816
#define DOF_ST    69632
#define DOF_KDT   34816
#define KDT_ARR   18432
#define KDT_PITCH 144
#define DOF_VNT   71680
#define VNT_ARR   9216
#define DELTA_SMEM_BYTES (82944 + 104448)   // 187392

__global__ __launch_bounds__(256, 1) void delta_kernel(
    const float* __restrict__ qn, const float* __restrict__ kn,
    const float* __restrict__ vv, const float* __restrict__ beta,
    const float* __restrict__ gg, float* __restrict__ core)
{
    extern __shared__ float sm[];
    char* smc = (char*)sm;
    uint32_t sbase = smem_u32(sm);
    float* st  = sm;          // [64 v][128 d]
    float* Vs  = st + 8192;   // [64 i][64 v]
    float* Wm  = Vs + 4096;   // [64][64]
    float* Am  = Wm + 4096;   // [64][64]
    float* gcs = Am + 4096;
    float* bet = gcs + 64;
    float* egs = bet + 64;
    float* edl = egs + 64;

    int t = threadIdx.x;
    int wrp = t >> 5, l = t & 31;
    int vs = blockIdx.x & 1;
    int h  = (blockIdx.x >> 1) & 31;
    int b  = blockIdx.x >> 6;
    int vo = vs * 64;
    int hk = h >> 1;
    const float* qb = qn + (size_t)(b*HKN+hk)*SS*128;
    const float* kb = kn + (size_t)(b*HKN+hk)*SS*128;
    const float* vb = vv + (size_t)(b*HVN+h)*SS*128;
    const float* bp = beta + (size_t)b*SS*HVN + h;
    const float* gp = gg   + (size_t)b*SS*HVN + h;
    float* cb = core + (size_t)(b*HVN+h)*SS*128;

    for (int i = t; i < 8192; i += 256) st[i] = 0.f;
    __syncthreads();

    for (int ck = 0; ck < NCHK; ck++) {
        size_t srow = (size_t)ck * 64;
        const float* qr = qb + srow*128;
        const float* kr = kb + srow*128;
        const float* vr = vb + srow*128;
        // staging: k/q/st bf16 hi/lo (float4 vectorized)
        for (int idx = t; idx < 2048; idx += 256) {
            int i = idx >> 5, d = (idx & 31) * 4;
            float4 kv = *(const float4*)&kr[i*128 + d];
            float4 qv = *(const float4*)&qr[i*128 + d];
            float4 svv = *(const float4*)&st[i*128 + d];
            int ro = i*DBF_PITCH + d*2;
            uint32_t kh0 = pack_bf2(kv.x, kv.y), kh1 = pack_bf2(kv.z, kv.w);
            uint32_t qh0 = pack_bf2(qv.x, qv.y), qh1 = pack_bf2(qv.z, qv.w);
            uint32_t sh0 = pack_bf2(svv.x, svv.y), sh1 = pack_bf2(svv.z, svv.w);
            *(uint32_t*)(smc + DBF_OFF + DOF_K + ro)     = kh0;
            *(uint32_t*)(smc + DBF_OFF + DOF_K + ro + 4) = kh1;
            *(uint32_t*)(smc + DBF_OFF + DOF_K + DBF_ARR + ro)     = pack_bf2_res(kv.x, kv.y, kh0);
            *(uint32_t*)(smc + DBF_OFF + DOF_K + DBF_ARR + ro + 4) = pack_bf2_res(kv.z, kv.w, kh1);
            *(uint32_t*)(smc + DBF_OFF + DOF_Q + ro)     = qh0;
            *(uint32_t*)(smc + DBF_OFF + DOF_Q + ro + 4) = qh1;
            *(uint32_t*)(smc + DBF_OFF + DOF_Q + DBF_ARR + ro)     = pack_bf2_res(qv.x, qv.y, qh0);
            *(uint32_t*)(smc + DBF_OFF + DOF_Q + DBF_ARR + ro + 4) = pack_bf2_res(qv.z, qv.w, qh1);
            *(uint32_t*)(smc + DBF_OFF + DOF_ST + ro)     = sh0;
            *(uint32_t*)(smc + DBF_OFF + DOF_ST + ro + 4) = sh1;
            *(uint32_t*)(smc + DBF_OFF + DOF_ST + DBF_ARR + ro)     = pack_bf2_res(svv.x, svv.y, sh0);
            *(uint32_t*)(smc + DBF_OFF + DOF_ST + DBF_ARR + ro + 4) = pack_bf2_res(svv.z, svv.w, sh1);
        }
        for (int idx = t; idx < 1024; idx += 256) {
            int i = idx >> 4, c = (idx & 15) * 4;
            *(float4*)&Vs[i*64 + c] = *(const float4*)&vr[i*128 + vo + c];
        }
        if (t < 64) {
            bet[t] = bp[(srow + t)*HVN];
            edl[t] = gp[(srow + t)*HVN];   // raw g
        }
        __syncthreads();
        // warp-scan prefix sum over 64 gate values
        if (t < 32) {
            float a = edl[2*t], b2 = edl[2*t+1];
            float run = a + b2;
#pragma unroll
            for (int o = 1; o < 32; o <<= 1) {
                float n = __shfl_up_sync(0xffffffffu, run, o);
                if (t >= o) run += n;
            }
            gcs[2*t+1] = run;
            gcs[2*t]   = run - b2;
        }
        __syncthreads();
        if (t < 64) {
            egs[t] = expf(gcs[t]);
            edl[t] = expf(gcs[63] - gcs[t]);
        }
        __syncthreads();

        // ---- 4 products (bf16x3): 0:W=K.K^T  1:A=Q.K^T  2:X'=K.S^T  3:O1=Q.S^T
        {
            uint32_t a_row = (l & 15);
            uint32_t a_col = (l >> 4) * 16;
            uint32_t b_row = (l & 7) + ((l >> 4) << 3);
            uint32_t b_col = ((l >> 3) & 1) * 16;
#pragma unroll
            for (int tt = 0; tt < 4; tt++) {
                int tile = wrp + tt*8;
                int prod = tile >> 3;
                int sub = tile & 7;
                int r0 = (sub >> 1) << 4, c0g = (sub & 1) << 5;
                uint32_t abase = sbase + DBF_OFF + ((prod & 1) ? DOF_Q : DOF_K);
                uint32_t bbase = sbase + DBF_OFF + ((prod >> 1) ? DOF_ST : DOF_K);
                float acc[4][4];
#pragma unroll
                for (int a2 = 0; a2 < 4; a2++)
#pragma unroll
                    for (int a3 = 0; a3 < 4; a3++) acc[a2][a3] = 0.f;
#pragma unroll
                for (int kt = 0; kt < 8; kt++) {
                    uint32_t aaddr = abase + (r0 + a_row)*DBF_PITCH + kt*32 + a_col;
                    uint32_t ah[4], al[4];
                    ldsm4(ah, aaddr);
                    ldsm4(al, aaddr + DBF_ARR);
#pragma unroll
                    for (int nn = 0; nn < 2; nn++) {
                        uint32_t baddr = bbase + (c0g + nn*16 + b_row)*DBF_PITCH + kt*32 + b_col;
                        uint32_t bh[4], bl[4];
                        ldsm4(bh, baddr);
                        ldsm4(bl, baddr + DBF_ARR);
                        mma16816b(acc[2*nn],   ah, bh);
                        mma16816b(acc[2*nn],   ah, bl);
                        mma16816b(acc[2*nn],   al, bh);
                        mma16816b(acc[2*nn+1], ah, bh + 2);
                        mma16816b(acc[2*nn+1], ah, bl + 2);
                        mma16816b(acc[2*nn+1], al, bh + 2);
                    }
                }
#pragma unroll
                for (int n8 = 0; n8 < 4; n8++) {
#pragma unroll
                    for (int e = 0; e < 4; e++) {
                        int row = r0 + (l >> 2) + ((e >> 1) ? 8 : 0);
                        int col = c0g + n8*8 + 2*(l & 3) + (e & 1);
                        float dot = acc[n8][e];
                        if (prod == 0) {
                            float outv = 0.f;
                            if (col < row) outv = bet[row] * expf(gcs[row] - gcs[col]) * dot;
                            Wm[row*64 + col] = outv;
                        } else if (prod == 1) {
                            float outv = 0.f;
                            if (col <= row) outv = expf(gcs[row] - gcs[col]) * dot;
                            Am[row*64 + col] = outv;
                        } else if (prod == 2) {
                            Vs[row*64 + col] = bet[row] * (Vs[row*64 + col] - egs[row] * dot);
                        } else {
                            cb[(srow + row)*128 + vo + col] = egs[row] * dot;
                        }
                    }
                }
            }
        }
        __syncthreads();
        // ---- fsub (t<64, stages VnT from registers) | KdT staging (t>=64) ----
        if (t < 64) {
            float x[64];
#pragma unroll
            for (int i = 0; i < 64; i++) {
                float a0 = Vs[i*64 + t], a1 = 0.f;
                int j = 0;
#pragma unroll
                for (; j + 2 <= i; j += 2) {
                    a0 -= Wm[i*64 + j]   * x[j];
                    a1 -= Wm[i*64 + j+1] * x[j+1];
                }
                if (j < i) a0 -= Wm[i*64 + j] * x[j];
                x[i] = a0 + a1;
            }
#pragma unroll
            for (int i = 0; i < 64; i++) Vs[i*64 + t] = x[i];
            // stage VnT row t (v = t), cols i
#pragma unroll
            for (int i2 = 0; i2 < 32; i2++) {
                uint32_t hi = pack_bf2(x[2*i2], x[2*i2+1]);
                *(uint32_t*)(smc + DBF_OFF + DOF_VNT + t*KDT_PITCH + i2*4) = hi;
                *(uint32_t*)(smc + DBF_OFF + DOF_VNT + VNT_ARR + t*KDT_PITCH + i2*4) =
                    pack_bf2_res(x[2*i2], x[2*i2+1], hi);
            }
        } else {
            // stage KdT[d][i] = k[i][d]*edl[i], bf16 hi/lo
            for (int idx = t - 64; idx < 4096; idx += 192) {
                int d = idx >> 5, ip = idx & 31;
                int i0 = 2*ip;
                float e0 = edl[i0], e1 = edl[i0+1];
                float k0 = (__bfloat162float(*(__nv_bfloat16*)(smc + DBF_OFF + DOF_K + i0*DBF_PITCH + d*2))
                          + __bfloat162float(*(__nv_bfloat16*)(smc + DBF_OFF + DOF_K + DBF_ARR + i0*DBF_PITCH + d*2))) * e0;
                float k1 = (__bfloat162float(*(__nv_bfloat16*)(smc + DBF_OFF + DOF_K + (i0+1)*DBF_PITCH + d*2))
                          + __bfloat162float(*(__nv_bfloat16*)(smc + DBF_OFF + DOF_K + DBF_ARR + (i0+1)*DBF_PITCH + d*2))) * e1;
                uint32_t hi = pack_bf2(k0, k1);
                *(uint32_t*)(smc + DBF_OFF + DOF_KDT + d*KDT_PITCH + ip*4) = hi;
                *(uint32_t*)(smc + DBF_OFF + DOF_KDT + KDT_ARR + d*KDT_PITCH + ip*4) = pack_bf2_res(k0, k1, hi);
            }
        }
        __syncthreads();
        // ---- out: cb += Am @ v_new (scalar) ----
        {
            int r0 = (t >> 3) * 2, c0 = (t & 7) * 8;
            float o2[2][8];
#pragma unroll
            for (int i = 0; i < 2; i++)
#pragma unroll
                for (int j = 0; j < 8; j++) o2[i][j] = 0.f;
            for (int jj = 0; jj < 64; jj++) {
                float a0 = Am[r0*64 + jj], a1 = Am[(r0+1)*64 + jj];
                float4 v0 = *(float4*)&Vs[jj*64 + c0];
                float4 v1 = *(float4*)&Vs[jj*64 + c0 + 4];
                float vw[8] = {v0.x,v0.y,v0.z,v0.w,v1.x,v1.y,v1.z,v1.w};
#pragma unroll
                for (int j = 0; j < 8; j++) {
                    o2[0][j] += a0*vw[j];
                    o2[1][j] += a1*vw[j];
                }
            }
#pragma unroll
            for (int i = 0; i < 2; i++) {
                int r = r0 + i;
#pragma unroll
                for (int j = 0; j < 8; j += 4) {
                    float4 v = *(float4*)&cb[(srow + r)*128 + vo + c0 + j];
                    v.x += o2[i][j];
                    v.y += o2[i][j+1];
                    v.z += o2[i][j+2];
                    v.w += o2[i][j+3];
                    *(float4*)&cb[(srow + r)*128 + vo + c0 + j] = v;
                }
            }
        }
        // ---- state update (tensor): st[v][d] = st*egl + (VnT @ KdT^T)[v][d], bf16x3 ----
        {
            int wv0 = (wrp & 3) * 16;
            int wd0 = (wrp >> 2) * 64;
            uint32_t a_row = (l & 15);
            uint32_t a_col = (l >> 4) * 16;
            uint32_t b_row = (l & 7) + ((l >> 4) << 3);
            uint32_t b_col = ((l >> 3) & 1) * 16;
            float acc[8][4];
#pragma unroll
            for (int i = 0; i < 8; i++)
#pragma unroll
                for (int j = 0; j < 4; j++) acc[i][j] = 0.f;
            uint32_t abase = sbase + DBF_OFF + DOF_VNT + (wv0 + a_row)*KDT_PITCH + a_col;
            uint32_t bbase = sbase + DBF_OFF + DOF_KDT + (wd0 + b_row)*KDT_PITCH + b_col;
#pragma unroll
            for (int kt2 = 0; kt2 < 4; kt2++) {
                uint32_t ah[4], al[4];
                ldsm4(ah, abase + kt2*32);
                ldsm4(al, abase + kt2*32 + VNT_ARR);
#pragma unroll
                for (int np = 0; np < 4; np++) {
                    uint32_t bh[4], bl[4];
                    ldsm4(bh, bbase + np*16*KDT_PITCH + kt2*32);
                    ldsm4(bl, bbase + np*16*KDT_PITCH + kt2*32 + KDT_ARR);
#pragma unroll
                    for (int half = 0; half < 2; half++) {
                        int n8 = 2*np + half;
                        mma16816b(acc[n8], ah, bh + 2*half);
                        mma16816b(acc[n8], ah, bl + 2*half);
                        mma16816b(acc[n8], al, bh + 2*half);
                    }
                }
            }
            float egl = expf(gcs[63]);
#pragma unroll
            for (int n8 = 0; n8 < 8; n8++) {
#pragma unroll
                for (int e = 0; e < 4; e++) {
                    int row = wv0 + (l >> 2) + ((e >> 1) ? 8 : 0);
                    int col = wd0 + n8*8 + 2*(l & 3) + (e & 1);
                    st[row*128 + col] = st[row*128 + col]*egl + acc[n8][e];
                }
            }
        }
        __syncthreads();
    }
}

// ---------------- gated RMSNorm + SiLU(z) gate -> fp16 hi/lo ----------------
__global__ __launch_bounds__(128) void normgate_kernel(
    const float* __restrict__ core, const float* __restrict__ z,
    const float* __restrict__ norm_weight,
    __half* __restrict__ act_hi, __half* __restrict__ act_lo)
{
    int s = blockIdx.x, h = blockIdx.y, b = blockIdx.z;
    int d = threadIdx.x;
    __shared__ float red[4];
    size_t ci = ((size_t)(b*HVN + h)*SS + s)*128 + d;
    float v = core[ci];
    float ss = v*v;
#pragma unroll
    for (int off = 16; off > 0; off >>= 1) ss += __shfl_down_sync(0xffffffffu, ss, off);
    if ((d & 31) == 0) red[d >> 5] = ss;
    __syncthreads();
    float var = (red[0]+red[1]+red[2]+red[3]) * (1.f/128.f);
    float scale = rsqrtf(var + 1e-6f) * norm_weight[d];
    size_t zi = ((size_t)b*SS + s)*VALD + h*128 + d;
    float zv = z[zi];
    float gate = zv / (1.f + expf(-zv));
    float val = v * scale * gate;
    __half hv = __float2half_rn(val);
    act_hi[zi] = hv;
    act_lo[zi] = __float2half_rn(val - __half2float(hv));
}

extern "C" void kernel_launch(void* const* d_in, const int* in_sizes, int n_in,
                              void* d_out, int out_size) {
    const float* hs     = (const float*)d_in[0];
    const float* W_qkv  = (const float*)d_in[1];
    const float* conv_w = (const float*)d_in[2];
    const float* W_z    = (const float*)d_in[3];
    const float* W_b    = (const float*)d_in[4];
    const float* W_a    = (const float*)d_in[5];
    const float* dt_b   = (const float*)d_in[6];
    const float* A_log  = (const float*)d_in[7];
    const float* normw  = (const float*)d_in[8];
    const float* W_out  = (const float*)d_in[9];
    float* out = (float*)d_out;

    float *mixed, *z, *qn, *kn, *v, *core, *beta, *gg;
    cudaGetSymbolAddress((void**)&mixed, g_mixed);
    cudaGetSymbolAddress((void**)&z,     g_z);
    cudaGetSymbolAddress((void**)&qn,    g_qn);
    cudaGetSymbolAddress((void**)&kn,    g_kn);
    cudaGetSymbolAddress((void**)&v,     g_v);
    cudaGetSymbolAddress((void**)&core,  g_core);
    cudaGetSymbolAddress((void**)&beta,  g_beta);
    cudaGetSymbolAddress((void**)&gg,    g_gg);

    __half *hs_hi, *hs_lo, *wqkv_h, *wz_h, *wout_h, *act_hi, *act_lo;
    cudaGetSymbolAddress((void**)&hs_hi,  g_hs_hi);
    cudaGetSymbolAddress((void**)&hs_lo,  g_hs_lo);
    cudaGetSymbolAddress((void**)&wqkv_h, g_wqkv_h);
    cudaGetSymbolAddress((void**)&wz_h,   g_wz_h);
    cudaGetSymbolAddress((void**)&wout_h, g_wout_h);
    cudaGetSymbolAddress((void**)&act_hi, g_act_hi);
    cudaGetSymbolAddress((void**)&act_lo, g_act_lo);

    cudaFuncSetAttribute(delta_kernel, cudaFuncAttributeMaxDynamicSharedMemorySize, DELTA_SMEM_BYTES);
    cudaFuncSetAttribute(hmma_gemm_kernel, cudaFuncAttributeMaxDynamicSharedMemorySize, GEMM_SMEM);

    static cudaStream_t s2 = nullptr;
    static cudaEvent_t e0 = nullptr, e1 = nullptr, e_bg = nullptr, e_g2 = nullptr;
    if (s2 == nullptr) {
        cudaStreamCreateWithFlags(&s2, cudaStreamNonBlocking);
        cudaEventCreateWithFlags(&e0, cudaEventDisableTiming);
        cudaEventCreateWithFlags(&e1, cudaEventDisableTiming);
        cudaEventCreateWithFlags(&e_bg, cudaEventDisableTiming);
        cudaEventCreateWithFlags(&e_g2, cudaEventDisableTiming);
    }

    // fork immediately: bg needs only hs
    cudaEventRecord(e0, 0);
    cudaStreamWaitEvent(s2, e0, 0);
    bg_kernel<<<MROWS/BG_RG, 256, 0, s2>>>(hs, W_b, W_a, dt_b, A_log, beta, gg);
    cudaEventRecord(e_bg, s2);

    // origin: weight transposes + hs split
    tsplit_all_kernel<<<32768, 256>>>(W_qkv, wqkv_h, W_z, wz_h, W_out, wout_h);
    split_kernel<<<2048, 256>>>(hs, hs_hi, hs_lo, (size_t)MROWS*HIDN);
    cudaEventRecord(e1, 0);

    // s2: gemm2 after splits
    cudaStreamWaitEvent(s2, e1, 0);
    hmma_gemm_kernel<<<dim3(MROWS/128, VALD/128), 256, GEMM_SMEM, s2>>>(
        hs_hi, hs_lo, wz_h, z, MROWS, VALD, HIDN);
    cudaEventRecord(e_g2, s2);

    // origin main chain
    hmma_gemm_kernel<<<dim3(MROWS/128, CONVD/128), 256, GEMM_SMEM>>>(
        hs_hi, hs_lo, wqkv_h, mixed, MROWS, CONVD, HIDN);
    conv_silu_kernel<<<dim3(64, SS/8, BB), 128>>>(mixed, conv_w, qn, kn, v);
    cudaStreamWaitEvent(0, e_bg, 0);
    delta_kernel<<<BB*HVN*2, 256, DELTA_SMEM_BYTES>>>(qn, kn, v, beta, gg, core);

    // join: normgate needs z
    cudaStreamWaitEvent(0, e_g2, 0);
    normgate_kernel<<<dim3(SS, HVN, BB), 128>>>(core, z, normw, act_hi, act_lo);

    // out = act @ W_out
    hmma_gemm_kernel<<<dim3(MROWS/128, HIDN/128), 256, GEMM_SMEM>>>(
        act_hi, act_lo, wout_h, out, MROWS, HIDN, VALD);
}

// round 17
// speedup vs baseline: 1.1223x; 1.0412x over previous
#include <cuda_runtime.h>
#include <cuda_bf16.h>
#include <cuda_fp16.h>
#include <math.h>
#include <stdint.h>

#define BB    2
#define SS    4096
#define HIDN  2048
#define HVN   32
#define HKN   16
#define CONVD 8192
#define KEYD  2048
#define VALD  4096
#define NCHK  64
#define MROWS (BB*SS)

// ---------------- device scratch ----------------
__device__ float g_mixed[(size_t)BB*SS*CONVD];
__device__ float g_z    [(size_t)BB*SS*VALD];
__device__ float g_qn   [(size_t)BB*HKN*SS*128];
__device__ float g_kn   [(size_t)BB*HKN*SS*128];
__device__ float g_v    [(size_t)BB*HVN*SS*128];
__device__ float g_core [(size_t)BB*HVN*SS*128];
__device__ float g_beta [(size_t)BB*SS*HVN];
__device__ float g_gg   [(size_t)BB*SS*HVN];

__device__ __half g_hs_hi [(size_t)MROWS*HIDN];
__device__ __half g_hs_lo [(size_t)MROWS*HIDN];
__device__ __half g_wqkv_h[(size_t)CONVD*HIDN];  // [N,K]
__device__ __half g_wz_h  [(size_t)VALD*HIDN];
__device__ __half g_wout_h[(size_t)HIDN*VALD];
__device__ __half g_act_hi[(size_t)MROWS*VALD];
__device__ __half g_act_lo[(size_t)MROWS*VALD];

// ---------------- helpers ----------------
__device__ __forceinline__ uint32_t smem_u32(const void* p) {
    uint32_t a;
    asm("{ .reg .u64 t; cvta.to.shared.u64 t, %1; cvt.u32.u64 %0, t; }" : "=r"(a) : "l"(p));
    return a;
}
__device__ __forceinline__ void ldsm4(uint32_t* r, uint32_t addr) {
    asm volatile("ldmatrix.sync.aligned.m8n8.x4.shared.b16 {%0,%1,%2,%3}, [%4];"
        : "=r"(r[0]), "=r"(r[1]), "=r"(r[2]), "=r"(r[3]) : "r"(addr));
}
__device__ __forceinline__ void mma16816f(float* c, const uint32_t* a, const uint32_t* b) {
    asm volatile("mma.sync.aligned.m16n8k16.row.col.f32.f16.f16.f32 "
        "{%0,%1,%2,%3}, {%4,%5,%6,%7}, {%8,%9}, {%0,%1,%2,%3};"
        : "+f"(c[0]), "+f"(c[1]), "+f"(c[2]), "+f"(c[3])
        : "r"(a[0]), "r"(a[1]), "r"(a[2]), "r"(a[3]), "r"(b[0]), "r"(b[1]));
}
__device__ __forceinline__ void mma16816b(float* c, const uint32_t* a, const uint32_t* b) {
    asm volatile("mma.sync.aligned.m16n8k16.row.col.f32.bf16.bf16.f32 "
        "{%0,%1,%2,%3}, {%4,%5,%6,%7}, {%8,%9}, {%0,%1,%2,%3};"
        : "+f"(c[0]), "+f"(c[1]), "+f"(c[2]), "+f"(c[3])
        : "r"(a[0]), "r"(a[1]), "r"(a[2]), "r"(a[3]), "r"(b[0]), "r"(b[1]));
}
__device__ __forceinline__ void cp16(uint32_t dst, const void* src) {
    asm volatile("cp.async.cg.shared.global [%0], [%1], 16;" :: "r"(dst), "l"(src));
}
__device__ __forceinline__ uint32_t pack_bf2(float a, float b) {
    __nv_bfloat162 h;
    h.x = __float2bfloat16_rn(a);
    h.y = __float2bfloat16_rn(b);
    return *(uint32_t*)&h;
}
__device__ __forceinline__ uint32_t pack_bf2_res(float a, float b, uint32_t hi) {
    __nv_bfloat162 h = *(__nv_bfloat162*)&hi;
    __nv_bfloat162 r;
    r.x = __float2bfloat16_rn(a - __bfloat162float(h.x));
    r.y = __float2bfloat16_rn(b - __bfloat162float(h.y));
    return *(uint32_t*)&r;
}

// ---------------- split kernels (fp16 hi/lo) ----------------
__global__ __launch_bounds__(256) void split_kernel(
    const float* __restrict__ in, __half* __restrict__ hi, __half* __restrict__ lo, size_t n)
{
    size_t i = (size_t)blockIdx.x * 256 + threadIdx.x;
    size_t stride = (size_t)gridDim.x * 256;
    for (; i < n; i += stride) {
        float v = in[i];
        __half h = __float2half_rn(v);
        hi[i] = h;
        lo[i] = __float2half_rn(v - __half2float(h));
    }
}

__global__ __launch_bounds__(256) void tsplit_all_kernel(
    const float* __restrict__ Wq, __half* __restrict__ qh,
    const float* __restrict__ Wz, __half* __restrict__ zh,
    const float* __restrict__ Wo, __half* __restrict__ oh)
{
    __shared__ float tile[32][33];
    int n = blockIdx.x;
    const float* W; __half* Thi; int K, N, bx, by;
    if (n < 16384)      { W = Wq; Thi = qh; K = HIDN; N = CONVD; bx = n & 255; by = n >> 8; }
    else if (n < 24576) { n -= 16384; W = Wz; Thi = zh; K = HIDN; N = VALD; bx = n & 127; by = n >> 7; }
    else                { n -= 24576; W = Wo; Thi = oh; K = VALD; N = HIDN; bx = n & 63;  by = n >> 6; }
    int tx = threadIdx.x & 31, ty = threadIdx.x >> 5;
    for (int i = ty; i < 32; i += 8)
        tile[i][tx] = W[(size_t)(by*32 + i) * N + bx*32 + tx];
    __syncthreads();
    for (int i = ty; i < 32; i += 8)
        Thi[(size_t)(bx*32 + i) * K + by*32 + tx] = __float2half_rn(tile[tx][i]);
}

// ---------------- HMMA fp16x2 GEMM (proven) ----------------
#define GS_ROW   80
#define GS_ARR   (128*GS_ROW)
#define GS_STAGE (3*GS_ARR)
#define GEMM_SMEM (2*GS_STAGE)

__global__ __launch_bounds__(256, 2) void hmma_gemm_kernel(
    const __half* __restrict__ Ahi, const __half* __restrict__ Alo,
    const __half* __restrict__ Bh,
    float* __restrict__ C, int M, int N, int K)
{
    extern __shared__ char smem[];
    uint32_t sb = smem_u32(smem);
    int t = threadIdx.x;
    int m0 = blockIdx.x * 128;
    int n0 = blockIdx.y * 128;
    int w = t >> 5, l = t & 31;
    int wm = w & 3, wn = w >> 2;

    const __half* srcs[3] = { Ahi, Alo, Bh };
    int rowbase[3];
    rowbase[0] = m0; rowbase[1] = m0; rowbase[2] = n0;

    float acc[2][8][4];
#pragma unroll
    for (int i = 0; i < 2; i++)
#pragma unroll
        for (int j = 0; j < 8; j++)
#pragma unroll
            for (int r = 0; r < 4; r++) acc[i][j][r] = 0.f;

    int KT = K >> 5;

    auto load_stage = [&](int s, int k0) {
        uint32_t stb = sb + s * GS_STAGE;
#pragma unroll
        for (int c = 0; c < 6; c++) {
            int idx = t + c * 256;
            int arr = idx >> 9;
            int within = idx & 511;
            int row = within >> 2, ch = within & 3;
            const __half* src = srcs[arr] + (size_t)(rowbase[arr] + row) * K + k0 + ch * 8;
            cp16(stb + arr * GS_ARR + row * GS_ROW + ch * 16, src);
        }
        asm volatile("cp.async.commit_group;");
    };

    load_stage(0, 0);

    int a_off = (wm * 32 + (l & 15)) * GS_ROW + ((l >> 4) * 16);
    int b_off = (wn * 64 + (l & 7) + ((l >> 4) << 3)) * GS_ROW + (((l >> 3) & 1) * 16);

    for (int kt = 0; kt < KT; kt++) {
        if (kt + 1 < KT) load_stage((kt + 1) & 1, (kt + 1) << 5);
        if (kt + 1 < KT) asm volatile("cp.async.wait_group 1;");
        else             asm volatile("cp.async.wait_group 0;");
        __syncthreads();

        uint32_t stb = sb + (kt & 1) * GS_STAGE;
#pragma unroll
        for (int ks = 0; ks < 2; ks++) {
            uint32_t ah[2][4], al[2][4];
#pragma unroll
            for (int mt = 0; mt < 2; mt++) {
                uint32_t aa = stb + a_off + mt * 16 * GS_ROW + ks * 32;
                ldsm4(ah[mt], aa);
                ldsm4(al[mt], aa + GS_ARR);
            }
#pragma unroll
            for (int ntp = 0; ntp < 4; ntp++) {
                uint32_t ba = stb + 2 * GS_ARR + b_off + ntp * 16 * GS_ROW + ks * 32;
                uint32_t bh[4];
                ldsm4(bh, ba);
#pragma unroll
                for (int mt = 0; mt < 2; mt++) {
                    mma16816f(acc[mt][2*ntp],   ah[mt], bh);
                    mma16816f(acc[mt][2*ntp],   al[mt], bh);
                    mma16816f(acc[mt][2*ntp+1], ah[mt], bh + 2);
                    mma16816f(acc[mt][2*ntp+1], al[mt], bh + 2);
                }
            }
        }
        __syncthreads();
    }

#pragma unroll
    for (int mt = 0; mt < 2; mt++) {
        int row = m0 + wm * 32 + mt * 16 + (l >> 2);
        int colb = n0 + wn * 64 + 2 * (l & 3);
#pragma unroll
        for (int nt = 0; nt < 8; nt++) {
            int col = colb + nt * 8;
            float2 v0; v0.x = acc[mt][nt][0]; v0.y = acc[mt][nt][1];
            float2 v1; v1.x = acc[mt][nt][2]; v1.y = acc[mt][nt][3];
            *(float2*)&C[(size_t)row * N + col] = v0;
            *(float2*)&C[(size_t)(row + 8) * N + col] = v1;
        }
    }
}

// ---------------- beta / g projections ----------------
#define BG_RG 4
__global__ __launch_bounds__(256) void bg_kernel(
    const float* __restrict__ hs, const float* __restrict__ W_b, const float* __restrict__ W_a,
    const float* __restrict__ dt_bias, const float* __restrict__ A_log,
    float* __restrict__ beta, float* __restrict__ gg)
{
    __shared__ float hsm[BG_RG * HIDN];
    __shared__ float red[4 * BG_RG * 64];
    int r0 = blockIdx.x * BG_RG;
    int t = threadIdx.x;
    for (int o = t; o < BG_RG * HIDN / 4; o += 256)
        ((float4*)hsm)[o] = ((const float4*)(hs + (size_t)r0 * HIDN))[o];
    __syncthreads();

    int out = t & 63, part = t >> 6;
    const float* Wp = (out < 32) ? (W_b + out) : (W_a + out - 32);
    float acc[BG_RG];
#pragma unroll
    for (int r = 0; r < BG_RG; r++) acc[r] = 0.f;
    int kbase = part * (HIDN / 4);
    for (int kk = 0; kk < HIDN / 4; kk++) {
        int k = kbase + kk;
        float w2 = Wp[(size_t)k * 32];
#pragma unroll
        for (int r = 0; r < BG_RG; r++) acc[r] += hsm[r * HIDN + k] * w2;
    }
#pragma unroll
    for (int r = 0; r < BG_RG; r++) red[(part * BG_RG + r) * 64 + out] = acc[r];
    __syncthreads();

    int rr = t >> 6, oo = t & 63;
    float s = red[(0*BG_RG+rr)*64+oo] + red[(1*BG_RG+rr)*64+oo]
            + red[(2*BG_RG+rr)*64+oo] + red[(3*BG_RG+rr)*64+oo];
    size_t row = (size_t)r0 + rr;
    if (oo < 32) {
        beta[row * 32 + oo] = 1.f / (1.f + expf(-s));
    } else {
        int h = oo - 32;
        float x = s + dt_bias[h];
        float sp = (x > 20.f) ? x : log1pf(expf(x));
        gg[row * 32 + h] = -expf(A_log[h]) * sp;
    }
}

// ---------------- conv1d(K=4 causal) + SiLU + split + l2norm(q,k) ----------------
__global__ __launch_bounds__(128) void conv_silu_kernel(
    const float* __restrict__ mixed, const float* __restrict__ conv_w,
    float* __restrict__ qn, float* __restrict__ kn, float* __restrict__ vout)
{
    int unit = blockIdx.x;
    int s0 = blockIdx.y * 8;
    int b = blockIdx.z;
    int d = threadIdx.x;
    int base = (unit < 16) ? unit * 128
             : (unit < 32) ? KEYD + (unit - 16) * 128
             : 2 * KEYD + (unit - 32) * 128;
    int c = base + d;
    const float* mb = mixed + (size_t)b * SS * CONVD + c;

    float m[11];
#pragma unroll
    for (int j = 0; j < 11; j++) {
        int sp = s0 + j - 3;
        m[j] = (sp >= 0) ? mb[(size_t)sp * CONVD] : 0.f;
    }
    float w0 = conv_w[(size_t)c*4+0], w1 = conv_w[(size_t)c*4+1],
          w2 = conv_w[(size_t)c*4+2], w3 = conv_w[(size_t)c*4+3];
    float xs[8];
#pragma unroll
    for (int sp = 0; sp < 8; sp++) {
        float a = w0*m[sp] + w1*m[sp+1] + w2*m[sp+2] + w3*m[sp+3];
        xs[sp] = a / (1.f + expf(-a));
    }

    if (unit < 32) {
        __shared__ float red[8][4];
#pragma unroll
        for (int sp = 0; sp < 8; sp++) {
            float ss = xs[sp]*xs[sp];
#pragma unroll
            for (int off = 16; off > 0; off >>= 1) ss += __shfl_down_sync(0xffffffffu, ss, off);
            if ((d & 31) == 0) red[sp][d >> 5] = ss;
        }
        __syncthreads();
        float* dst; float extra;
        if (unit < 16) { dst = qn + (((size_t)(b*HKN+unit))*SS)*128; extra = 0.08838834764831845f; }
        else           { dst = kn + (((size_t)(b*HKN+unit-16))*SS)*128; extra = 1.f; }
#pragma unroll
        for (int sp = 0; sp < 8; sp++) {
            float tot = red[sp][0]+red[sp][1]+red[sp][2]+red[sp][3];
            float scale = rsqrtf(tot + 1e-6f) * extra;
            dst[(size_t)(s0+sp)*128 + d] = xs[sp] * scale;
        }
    } else {
        float* dst = vout + (((size_t)(b*HVN+unit-32))*SS)*128;
#pragma unroll
        for (int sp = 0; sp < 8; sp++)
            dst[(size_t)(s0+sp)*128 + d] = xs[sp];
    }
}

// ---------------- chunked gated delta rule: all matmuls on tensor cores, factorized decay ----------------
// fp32 floats: st[64v][128d] 8192 | Vs 4096 | Wm 4096 | gcs 64 | bet 64 | egs 64 | edl 64 | rex 64 | cex 1024
//            = 17728 floats = 70912 B
// bf16 region at DBF_OFF: K hi/lo (2x17408) | Q hi/lo | ST hi/lo (ends 104448) | AMB hi/lo (104448..122880)
// post-product overlays: KdT at DOF_Q (pitch 144), VnT at 71680 (inside dead ST)
#define DBF_OFF   70912
#define DBF_ARR   17408
#define DBF_PITCH 272
#define DOF_K     0
#define DOF_Q     34816
#define DOF_ST    69632
#define DOF_KDT   34816
#define KDT_ARR   18432
#define KDT_PITCH 144
#define DOF_VNT   71680
#define VNT_ARR   9216
#define DOF_AMB   104448
#define AMB_ARR   9216
#define DELTA_SMEM_BYTES (70912 + 122880)   // 193792

__global__ __launch_bounds__(256, 1) void delta_kernel(
    const float* __restrict__ qn, const float* __restrict__ kn,
    const float* __restrict__ vv, const float* __restrict__ beta,
    const float* __restrict__ gg, float* __restrict__ core)
{
    extern __shared__ float sm[];
    char* smc = (char*)sm;
    uint32_t sbase = smem_u32(sm);
    float* st  = sm;          // [64 v][128 d]
    float* Vs  = st + 8192;   // [64 i][64 v]
    float* Wm  = Vs + 4096;   // [64][64]
    float* gcs = Wm + 4096;
    float* bet = gcs + 64;
    float* egs = bet + 64;
    float* edl = egs + 64;
    float* rex = edl + 64;    // [64]
    float* cex = rex + 64;    // [16][64]

    int t = threadIdx.x;
    int wrp = t >> 5, l = t & 31;
    int vs = blockIdx.x & 1;
    int h  = (blockIdx.x >> 1) & 31;
    int b  = blockIdx.x >> 6;
    int vo = vs * 64;
    int hk = h >> 1;
    const float* qb = qn + (size_t)(b*HKN+hk)*SS*128;
    const float* kb = kn + (size_t)(b*HKN+hk)*SS*128;
    const float* vb = vv + (size_t)(b*HVN+h)*SS*128;
    const float* bp = beta + (size_t)b*SS*HVN + h;
    const float* gp = gg   + (size_t)b*SS*HVN + h;
    float* cb = core + (size_t)(b*HVN+h)*SS*128;

    for (int i = t; i < 8192; i += 256) st[i] = 0.f;
    __syncthreads();

    for (int ck = 0; ck < NCHK; ck++) {
        size_t srow = (size_t)ck * 64;
        const float* qr = qb + srow*128;
        const float* kr = kb + srow*128;
        const float* vr = vb + srow*128;
        // staging: k/q/st bf16 hi/lo (float4 vectorized)
        for (int idx = t; idx < 2048; idx += 256) {
            int i = idx >> 5, d = (idx & 31) * 4;
            float4 kv = *(const float4*)&kr[i*128 + d];
            float4 qv = *(const float4*)&qr[i*128 + d];
            float4 svv = *(const float4*)&st[i*128 + d];
            int ro = i*DBF_PITCH + d*2;
            uint32_t kh0 = pack_bf2(kv.x, kv.y), kh1 = pack_bf2(kv.z, kv.w);
            uint32_t qh0 = pack_bf2(qv.x, qv.y), qh1 = pack_bf2(qv.z, qv.w);
            uint32_t sh0 = pack_bf2(svv.x, svv.y), sh1 = pack_bf2(svv.z, svv.w);
            *(uint32_t*)(smc + DBF_OFF + DOF_K + ro)     = kh0;
            *(uint32_t*)(smc + DBF_OFF + DOF_K + ro + 4) = kh1;
            *(uint32_t*)(smc + DBF_OFF + DOF_K + DBF_ARR + ro)     = pack_bf2_res(kv.x, kv.y, kh0);
            *(uint32_t*)(smc + DBF_OFF + DOF_K + DBF_ARR + ro + 4) = pack_bf2_res(kv.z, kv.w, kh1);
            *(uint32_t*)(smc + DBF_OFF + DOF_Q + ro)     = qh0;
            *(uint32_t*)(smc + DBF_OFF + DOF_Q + ro + 4) = qh1;
            *(uint32_t*)(smc + DBF_OFF + DOF_Q + DBF_ARR + ro)     = pack_bf2_res(qv.x, qv.y, qh0);
            *(uint32_t*)(smc + DBF_OFF + DOF_Q + DBF_ARR + ro + 4) = pack_bf2_res(qv.z, qv.w, qh1);
            *(uint32_t*)(smc + DBF_OFF + DOF_ST + ro)     = sh0;
            *(uint32_t*)(smc + DBF_OFF + DOF_ST + ro + 4) = sh1;
            *(uint32_t*)(smc + DBF_OFF + DOF_ST + DBF_ARR + ro)     = pack_bf2_res(svv.x, svv.y, sh0);
            *(uint32_t*)(smc + DBF_OFF + DOF_ST + DBF_ARR + ro + 4) = pack_bf2_res(svv.z, svv.w, sh1);
        }
        for (int idx = t; idx < 1024; idx += 256) {
            int i = idx >> 4, c = (idx & 15) * 4;
            *(float4*)&Vs[i*64 + c] = *(const float4*)&vr[i*128 + vo + c];
        }
        if (t < 64) {
            bet[t] = bp[(srow + t)*HVN];
            edl[t] = gp[(srow + t)*HVN];   // raw g
        }
        __syncthreads();
        // warp-scan prefix sum over 64 gate values
        if (t < 32) {
            float a = edl[2*t], b2 = edl[2*t+1];
            float run = a + b2;
#pragma unroll
            for (int o = 1; o < 32; o <<= 1) {
                float n = __shfl_up_sync(0xffffffffu, run, o);
                if (t >= o) run += n;
            }
            gcs[2*t+1] = run;
            gcs[2*t]   = run - b2;
        }
        __syncthreads();
        if (t < 64) {
            egs[t] = __expf(gcs[t]);
            edl[t] = __expf(gcs[63] - gcs[t]);
            rex[t] = __expf(gcs[t] - gcs[t & ~3]);
        }
        for (int i = t; i < 1024; i += 256) {
            int rb = i >> 6, col = i & 63;
            cex[i] = __expf(gcs[rb*4] - gcs[col]);
        }
        __syncthreads();

        // ---- 4 products (bf16x3): 0:W=K.K^T  1:A=Q.K^T (->AMB bf16)  2:X'=K.S^T  3:O1=Q.S^T
        {
            uint32_t a_row = (l & 15);
            uint32_t a_col = (l >> 4) * 16;
            uint32_t b_row = (l & 7) + ((l >> 4) << 3);
            uint32_t b_col = ((l >> 3) & 1) * 16;
#pragma unroll
            for (int tt = 0; tt < 4; tt++) {
                int tile = wrp + tt*8;
                int prod = tile >> 3;
                int sub = tile & 7;
                int r0 = (sub >> 1) << 4, c0g = (sub & 1) << 5;
                uint32_t abase = sbase + DBF_OFF + ((prod & 1) ? DOF_Q : DOF_K);
                uint32_t bbase = sbase + DBF_OFF + ((prod >> 1) ? DOF_ST : DOF_K);
                float acc[4][4];
#pragma unroll
                for (int a2 = 0; a2 < 4; a2++)
#pragma unroll
                    for (int a3 = 0; a3 < 4; a3++) acc[a2][a3] = 0.f;
#pragma unroll
                for (int kt = 0; kt < 8; kt++) {
                    uint32_t aaddr = abase + (r0 + a_row)*DBF_PITCH + kt*32 + a_col;
                    uint32_t ah[4], al[4];
                    ldsm4(ah, aaddr);
                    ldsm4(al, aaddr + DBF_ARR);
#pragma unroll
                    for (int nn = 0; nn < 2; nn++) {
                        uint32_t baddr = bbase + (c0g + nn*16 + b_row)*DBF_PITCH + kt*32 + b_col;
                        uint32_t bh[4], bl[4];
                        ldsm4(bh, baddr);
                        ldsm4(bl, baddr + DBF_ARR);
                        mma16816b(acc[2*nn],   ah, bh);
                        mma16816b(acc[2*nn],   ah, bl);
                        mma16816b(acc[2*nn],   al, bh);
                        mma16816b(acc[2*nn+1], ah, bh + 2);
                        mma16816b(acc[2*nn+1], ah, bl + 2);
                        mma16816b(acc[2*nn+1], al, bh + 2);
                    }
                }
#pragma unroll
                for (int n8 = 0; n8 < 4; n8++) {
#pragma unroll
                    for (int e = 0; e < 4; e++) {
                        int row = r0 + (l >> 2) + ((e >> 1) ? 8 : 0);
                        int col = c0g + n8*8 + 2*(l & 3) + (e & 1);
                        float dot = acc[n8][e];
                        if (prod == 0) {
                            float outv = 0.f;
                            if (col < row) outv = bet[row] * rex[row] * cex[(row >> 2)*64 + col] * dot;
                            Wm[row*64 + col] = outv;
                        } else if (prod == 1) {
                            float av = 0.f;
                            if (col <= row) av = rex[row] * cex[(row >> 2)*64 + col] * dot;
                            uint32_t off = DBF_OFF + DOF_AMB + row*KDT_PITCH + col*2;
                            __nv_bfloat16 hi = __float2bfloat16_rn(av);
                            *(__nv_bfloat16*)(smc + off) = hi;
                            *(__nv_bfloat16*)(smc + off + AMB_ARR) = __float2bfloat16_rn(av - __bfloat162float(hi));
                        } else if (prod == 2) {
                            Vs[row*64 + col] = bet[row] * (Vs[row*64 + col] - egs[row] * dot);
                        } else {
                            cb[(srow + row)*128 + vo + col] = egs[row] * dot;
                        }
                    }
                }
            }
        }
        __syncthreads();
        // ---- fsub (t<64, stages VnT) | KdT staging (t>=64) ----
        if (t < 64) {
            float x[64];
#pragma unroll
            for (int i = 0; i < 64; i++) {
                float a0 = Vs[i*64 + t], a1 = 0.f;
                int j = 0;
#pragma unroll
                for (; j + 2 <= i; j += 2) {
                    a0 -= Wm[i*64 + j]   * x[j];
                    a1 -= Wm[i*64 + j+1] * x[j+1];
                }
                if (j < i) a0 -= Wm[i*64 + j] * x[j];
                x[i] = a0 + a1;
            }
            // stage VnT row t (v = t), cols i
#pragma unroll
            for (int i2 = 0; i2 < 32; i2++) {
                uint32_t hi = pack_bf2(x[2*i2], x[2*i2+1]);
                *(uint32_t*)(smc + DBF_OFF + DOF_VNT + t*KDT_PITCH + i2*4) = hi;
                *(uint32_t*)(smc + DBF_OFF + DOF_VNT + VNT_ARR + t*KDT_PITCH + i2*4) =
                    pack_bf2_res(x[2*i2], x[2*i2+1], hi);
            }
        } else {
            // stage KdT[d][i] = k[i][d]*edl[i], bf16 hi/lo
            for (int idx = t - 64; idx < 4096; idx += 192) {
                int d = idx >> 5, ip = idx & 31;
                int i0 = 2*ip;
                float e0 = edl[i0], e1 = edl[i0+1];
                float k0 = (__bfloat162float(*(__nv_bfloat16*)(smc + DBF_OFF + DOF_K + i0*DBF_PITCH + d*2))
                          + __bfloat162float(*(__nv_bfloat16*)(smc + DBF_OFF + DOF_K + DBF_ARR + i0*DBF_PITCH + d*2))) * e0;
                float k1 = (__bfloat162float(*(__nv_bfloat16*)(smc + DBF_OFF + DOF_K + (i0+1)*DBF_PITCH + d*2))
                          + __bfloat162float(*(__nv_bfloat16*)(smc + DBF_OFF + DOF_K + DBF_ARR + (i0+1)*DBF_PITCH + d*2))) * e1;
                uint32_t hi = pack_bf2(k0, k1);
                *(uint32_t*)(smc + DBF_OFF + DOF_KDT + d*KDT_PITCH + ip*4) = hi;
                *(uint32_t*)(smc + DBF_OFF + DOF_KDT + KDT_ARR + d*KDT_PITCH + ip*4) = pack_bf2_res(k0, k1, hi);
            }
        }
        __syncthreads();
        // ---- out (tensor): cb += Am @ Vn  (A=AMB rows i, B=VnT rows v), bf16x3 ----
        {
            int wi0 = (wrp & 3) * 16;
            int wv0 = (wrp >> 2) * 32;
            uint32_t a_row = (l & 15);
            uint32_t a_col = (l >> 4) * 16;
            uint32_t b_row = (l & 7) + ((l >> 4) << 3);
            uint32_t b_col = ((l >> 3) & 1) * 16;
            float acc[4][4];
#pragma unroll
            for (int i = 0; i < 4; i++)
#pragma unroll
                for (int j = 0; j < 4; j++) acc[i][j] = 0.f;
            uint32_t abase = sbase + DBF_OFF + DOF_AMB + (wi0 + a_row)*KDT_PITCH + a_col;
            uint32_t bbase = sbase + DBF_OFF + DOF_VNT + (wv0 + b_row)*KDT_PITCH + b_col;
#pragma unroll
            for (int kt2 = 0; kt2 < 4; kt2++) {
                uint32_t ah[4], al[4];
                ldsm4(ah, abase + kt2*32);
                ldsm4(al, abase + kt2*32 + AMB_ARR);
#pragma unroll
                for (int np = 0; np < 2; np++) {
                    uint32_t bh[4], bl[4];
                    ldsm4(bh, bbase + np*16*KDT_PITCH + kt2*32);
                    ldsm4(bl, bbase + np*16*KDT_PITCH + kt2*32 + VNT_ARR);
#pragma unroll
                    for (int half = 0; half < 2; half++) {
                        int n8 = 2*np + half;
                        mma16816b(acc[n8], ah, bh + 2*half);
                        mma16816b(acc[n8], ah, bl + 2*half);
                        mma16816b(acc[n8], al, bh + 2*half);
                    }
                }
            }
#pragma unroll
            for (int n8 = 0; n8 < 4; n8++) {
#pragma unroll
                for (int e = 0; e < 4; e++) {
                    int row = wi0 + (l >> 2) + ((e >> 1) ? 8 : 0);
                    int col = wv0 + n8*8 + 2*(l & 3) + (e & 1);
                    cb[(srow + row)*128 + vo + col] += acc[n8][e];
                }
            }
        }
        // ---- state update (tensor): st[v][d] = st*egl + (VnT @ KdT^T)[v][d], bf16x3 ----
        {
            int wv0 = (wrp & 3) * 16;
            int wd0 = (wrp >> 2) * 64;
            uint32_t a_row = (l & 15);
            uint32_t a_col = (l >> 4) * 16;
            uint32_t b_row = (l & 7) + ((l >> 4) << 3);
            uint32_t b_col = ((l >> 3) & 1) * 16;
            float acc[8][4];
#pragma unroll
            for (int i = 0; i < 8; i++)
#pragma unroll
                for (int j = 0; j < 4; j++) acc[i][j] = 0.f;
            uint32_t abase = sbase + DBF_OFF + DOF_VNT + (wv0 + a_row)*KDT_PITCH + a_col;
            uint32_t bbase = sbase + DBF_OFF + DOF_KDT + (wd0 + b_row)*KDT_PITCH + b_col;
#pragma unroll
            for (int kt2 = 0; kt2 < 4; kt2++) {
                uint32_t ah[4], al[4];
                ldsm4(ah, abase + kt2*32);
                ldsm4(al, abase + kt2*32 + VNT_ARR);
#pragma unroll
                for (int np = 0; np < 4; np++) {
                    uint32_t bh[4], bl[4];
                    ldsm4(bh, bbase + np*16*KDT_PITCH + kt2*32);
                    ldsm4(bl, bbase + np*16*KDT_PITCH + kt2*32 + KDT_ARR);
#pragma unroll
                    for (int half = 0; half < 2; half++) {
                        int n8 = 2*np + half;
                        mma16816b(acc[n8], ah, bh + 2*half);
                        mma16816b(acc[n8], ah, bl + 2*half);
                        mma16816b(acc[n8], al, bh + 2*half);
                    }
                }
            }
            float egl = __expf(gcs[63]);
#pragma unroll
            for (int n8 = 0; n8 < 8; n8++) {
#pragma unroll
                for (int e = 0; e < 4; e++) {
                    int row = wv0 + (l >> 2) + ((e >> 1) ? 8 : 0);
                    int col = wd0 + n8*8 + 2*(l & 3) + (e & 1);
                    st[row*128 + col] = st[row*128 + col]*egl + acc[n8][e];
                }
            }
        }
        __syncthreads();
    }
}

// ---------------- gated RMSNorm + SiLU(z) gate -> fp16 hi/lo ----------------
__global__ __launch_bounds__(128) void normgate_kernel(
    const float* __restrict__ core, const float* __restrict__ z,
    const float* __restrict__ norm_weight,
    __half* __restrict__ act_hi, __half* __restrict__ act_lo)
{
    int s = blockIdx.x, h = blockIdx.y, b = blockIdx.z;
    int d = threadIdx.x;
    __shared__ float red[4];
    size_t ci = ((size_t)(b*HVN + h)*SS + s)*128 + d;
    float v = core[ci];
    float ss = v*v;
#pragma unroll
    for (int off = 16; off > 0; off >>= 1) ss += __shfl_down_sync(0xffffffffu, ss, off);
    if ((d & 31) == 0) red[d >> 5] = ss;
    __syncthreads();
    float var = (red[0]+red[1]+red[2]+red[3]) * (1.f/128.f);
    float scale = rsqrtf(var + 1e-6f) * norm_weight[d];
    size_t zi = ((size_t)b*SS + s)*VALD + h*128 + d;
    float zv = z[zi];
    float gate = zv / (1.f + expf(-zv));
    float val = v * scale * gate;
    __half hv = __float2half_rn(val);
    act_hi[zi] = hv;
    act_lo[zi] = __float2half_rn(val - __half2float(hv));
}

extern "C" void kernel_launch(void* const* d_in, const int* in_sizes, int n_in,
                              void* d_out, int out_size) {
    const float* hs     = (const float*)d_in[0];
    const float* W_qkv  = (const float*)d_in[1];
    const float* conv_w = (const float*)d_in[2];
    const float* W_z    = (const float*)d_in[3];
    const float* W_b    = (const float*)d_in[4];
    const float* W_a    = (const float*)d_in[5];
    const float* dt_b   = (const float*)d_in[6];
    const float* A_log  = (const float*)d_in[7];
    const float* normw  = (const float*)d_in[8];
    const float* W_out  = (const float*)d_in[9];
    float* out = (float*)d_out;

    float *mixed, *z, *qn, *kn, *v, *core, *beta, *gg;
    cudaGetSymbolAddress((void**)&mixed, g_mixed);
    cudaGetSymbolAddress((void**)&z,     g_z);
    cudaGetSymbolAddress((void**)&qn,    g_qn);
    cudaGetSymbolAddress((void**)&kn,    g_kn);
    cudaGetSymbolAddress((void**)&v,     g_v);
    cudaGetSymbolAddress((void**)&core,  g_core);
    cudaGetSymbolAddress((void**)&beta,  g_beta);
    cudaGetSymbolAddress((void**)&gg,    g_gg);

    __half *hs_hi, *hs_lo, *wqkv_h, *wz_h, *wout_h, *act_hi, *act_lo;
    cudaGetSymbolAddress((void**)&hs_hi,  g_hs_hi);
    cudaGetSymbolAddress((void**)&hs_lo,  g_hs_lo);
    cudaGetSymbolAddress((void**)&wqkv_h, g_wqkv_h);
    cudaGetSymbolAddress((void**)&wz_h,   g_wz_h);
    cudaGetSymbolAddress((void**)&wout_h, g_wout_h);
    cudaGetSymbolAddress((void**)&act_hi, g_act_hi);
    cudaGetSymbolAddress((void**)&act_lo, g_act_lo);

    cudaFuncSetAttribute(delta_kernel, cudaFuncAttributeMaxDynamicSharedMemorySize, DELTA_SMEM_BYTES);
    cudaFuncSetAttribute(hmma_gemm_kernel, cudaFuncAttributeMaxDynamicSharedMemorySize, GEMM_SMEM);

    static cudaStream_t s2 = nullptr;
    static cudaEvent_t e0 = nullptr, e1 = nullptr, e_bg = nullptr, e_g2 = nullptr;
    if (s2 == nullptr) {
        cudaStreamCreateWithFlags(&s2, cudaStreamNonBlocking);
        cudaEventCreateWithFlags(&e0, cudaEventDisableTiming);
        cudaEventCreateWithFlags(&e1, cudaEventDisableTiming);
        cudaEventCreateWithFlags(&e_bg, cudaEventDisableTiming);
        cudaEventCreateWithFlags(&e_g2, cudaEventDisableTiming);
    }

    // fork immediately: bg needs only hs
    cudaEventRecord(e0, 0);
    cudaStreamWaitEvent(s2, e0, 0);
    bg_kernel<<<MROWS/BG_RG, 256, 0, s2>>>(hs, W_b, W_a, dt_b, A_log, beta, gg);
    cudaEventRecord(e_bg, s2);

    // origin: weight transposes + hs split
    tsplit_all_kernel<<<32768, 256>>>(W_qkv, wqkv_h, W_z, wz_h, W_out, wout_h);
    split_kernel<<<2048, 256>>>(hs, hs_hi, hs_lo, (size_t)MROWS*HIDN);
    cudaEventRecord(e1, 0);

    // s2: gemm2 after splits
    cudaStreamWaitEvent(s2, e1, 0);
    hmma_gemm_kernel<<<dim3(MROWS/128, VALD/128), 256, GEMM_SMEM, s2>>>(
        hs_hi, hs_lo, wz_h, z, MROWS, VALD, HIDN);
    cudaEventRecord(e_g2, s2);

    // origin main chain
    hmma_gemm_kernel<<<dim3(MROWS/128, CONVD/128), 256, GEMM_SMEM>>>(
        hs_hi, hs_lo, wqkv_h, mixed, MROWS, CONVD, HIDN);
    conv_silu_kernel<<<dim3(64, SS/8, BB), 128>>>(mixed, conv_w, qn, kn, v);
    cudaStreamWaitEvent(0, e_bg, 0);
    delta_kernel<<<BB*HVN*2, 256, DELTA_SMEM_BYTES>>>(qn, kn, v, beta, gg, core);

    // join: normgate needs z
    cudaStreamWaitEvent(0, e_g2, 0);
    normgate_kernel<<<dim3(SS, HVN, BB), 128>>>(core, z, normw, act_hi, act_lo);

    // out = act @ W_out
    hmma_gemm_kernel<<<dim3(MROWS/128, HIDN/128), 256, GEMM_SMEM>>>(
        act_hi, act_lo, wout_h, out, MROWS, HIDN, VALD);
}